// round 14
// baseline (speedup 1.0000x reference)
#include <cuda_runtime.h>
#include <cuda_fp16.h>
#include <stdint.h>
#include <math.h>

// ---------------- problem constants ----------------
#define BB      8
#define TT      4
#define NPTS    1024
#define MPTS    4096
#define CIN     256
#define CORIG   128
#define CCAT    384
#define P1      256
#define P2      256
#define FRAMES  32          // B*T
#define EPS_D   1e-8f
#define EPS_BN  1e-5f

// ---------------- scratch (device globals, no runtime alloc) ----------------
__device__ __align__(16) int   g_idx[FRAMES * MPTS * 3];
__device__ __align__(16) float g_w  [FRAMES * MPTS * 3];
__device__ __align__(16) float g_ZT [(size_t)FRAMES * NPTS * P1];     // [f][n][o]
__device__ __align__(16) float g_y1 [(size_t)FRAMES * MPTS * P1];     // [f][m][o]
__device__ __align__(16) float g_y2 [(size_t)FRAMES * MPTS * P2];     // [f][m][o]
// fp16 weights, [k][n] layout (n contiguous)
__device__ __align__(16) __half g_W1a[CIN * P1];
__device__ __align__(16) __half g_W1b[CORIG * P1];
__device__ __align__(16) __half g_W2 [P1 * P2];
__device__ float g_sum1[TT * P1], g_sq1[TT * P1], g_a1[TT * P1], g_b1[TT * P1];
__device__ float g_sum2[TT * P2], g_sq2[TT * P2], g_a2[TT * P2], g_b2[TT * P2];

// ---------------- helpers ----------------
__device__ __forceinline__ uint32_t smem_u32(const void* p) {
    uint32_t a;
    asm("{ .reg .u64 t; cvta.to.shared.u64 t, %1; cvt.u32.u64 %0, t; }" : "=r"(a) : "l"(p));
    return a;
}

#define LDMX4(r, addr) \
    asm volatile("ldmatrix.sync.aligned.m8n8.x4.shared.b16 {%0,%1,%2,%3}, [%4];" \
        : "=r"((r)[0]), "=r"((r)[1]), "=r"((r)[2]), "=r"((r)[3]) : "r"(addr))

#define LDMX4T(r, addr) \
    asm volatile("ldmatrix.sync.aligned.m8n8.x4.trans.shared.b16 {%0,%1,%2,%3}, [%4];" \
        : "=r"((r)[0]), "=r"((r)[1]), "=r"((r)[2]), "=r"((r)[3]) : "r"(addr))

#define MMA_F16(d, a, b0, b1) \
    asm volatile("mma.sync.aligned.m16n8k16.row.col.f32.f16.f16.f32 " \
        "{%0,%1,%2,%3},{%4,%5,%6,%7},{%8,%9},{%0,%1,%2,%3};" \
        : "+f"((d)[0]), "+f"((d)[1]), "+f"((d)[2]), "+f"((d)[3]) \
        : "r"((a)[0]), "r"((a)[1]), "r"((a)[2]), "r"((a)[3]), "r"(b0), "r"(b1))

#define CP_ASYNC16(dst, src) \
    asm volatile("cp.async.cg.shared.global [%0], [%1], 16;" :: "r"(dst), "l"(src))
#define CP_COMMIT()  asm volatile("cp.async.commit_group;" ::: "memory")
#define CP_WAIT0()   asm volatile("cp.async.wait_group 0;" ::: "memory")
#define CP_WAIT1()   asm volatile("cp.async.wait_group 1;" ::: "memory")

// fp16 hi/lo split of two floats
__device__ __forceinline__ void split2(float a, float b, uint32_t& h, uint32_t& l) {
    __half2 hb = __floats2half2_rn(a, b);
    float2 hf = __half22float2(hb);
    __half2 lb = __floats2half2_rn(a - hf.x, b - hf.y);
    h = *reinterpret_cast<uint32_t*>(&hb);
    l = *reinterpret_cast<uint32_t*>(&lb);
}

// ---------------- prep ----------------
__global__ void prep_kernel(const float* __restrict__ W1, const float* __restrict__ W2) {
    int i = blockIdx.x * 256 + threadIdx.x;
    if (i < TT * P1) { g_sum1[i] = 0.f; g_sq1[i] = 0.f; g_sum2[i] = 0.f; g_sq2[i] = 0.f; }
    if (i < P1 * CCAT) {
        int o = i / CCAT, c = i % CCAT;
        __half h = __float2half_rn(W1[i]);
        if (c < CIN) g_W1a[c * P1 + o] = h;
        else         g_W1b[(c - CIN) * P1 + o] = h;
    }
    if (i < P2 * P1) {
        int o = i / P1, c = i % P1;
        g_W2[c * P2 + o] = __float2half_rn(W2[i]);
    }
}

// ---------------- three_nn: 4 m-points per thread (LDS amortized 4x) ----------------
__global__ void knn_kernel(const float* __restrict__ xyzs, const float* __restrict__ oxyzs) {
    __shared__ float sx[NPTS], sy[NPTS], sz[NPTS];
    int f = blockIdx.y;
    const float* p = xyzs + (size_t)f * NPTS * 3;
    for (int i = threadIdx.x; i < NPTS; i += 256) {
        sx[i] = p[3 * i]; sy[i] = p[3 * i + 1]; sz[i] = p[3 * i + 2];
    }
    __syncthreads();

    float qx[4], qy[4], qz[4];
    float b0[4], b1[4], b2[4];
    int   j0[4], j1[4], j2[4];
    #pragma unroll
    for (int k = 0; k < 4; k++) {
        int m = blockIdx.x * 256 + threadIdx.x + k * 1024;
        const float* q = oxyzs + ((size_t)f * MPTS + m) * 3;
        qx[k] = q[0]; qy[k] = q[1]; qz[k] = q[2];
        b0[k] = 1e30f; b1[k] = 1e30f; b2[k] = 1e30f;
        j0[k] = 0; j1[k] = 0; j2[k] = 0;
    }
    #pragma unroll 2
    for (int n = 0; n < NPTS; n++) {
        float x = sx[n], y = sy[n], z = sz[n];
        #pragma unroll
        for (int k = 0; k < 4; k++) {
            float dx = qx[k] - x, dy = qy[k] - y, dz = qz[k] - z;
            float d = fmaf(dx, dx, fmaf(dy, dy, dz * dz));
            if (d < b2[k]) {
                if (d < b1[k]) {
                    b2[k] = b1[k]; j2[k] = j1[k];
                    if (d < b0[k]) { b1[k] = b0[k]; j1[k] = j0[k]; b0[k] = d; j0[k] = n; }
                    else           { b1[k] = d;     j1[k] = n; }
                } else { b2[k] = d; j2[k] = n; }
            }
        }
    }
    #pragma unroll
    for (int k = 0; k < 4; k++) {
        int m = blockIdx.x * 256 + threadIdx.x + k * 1024;
        float w0 = 1.f / (b0[k] + EPS_D), w1 = 1.f / (b1[k] + EPS_D), w2 = 1.f / (b2[k] + EPS_D);
        float inv = 1.f / (w0 + w1 + w2);
        size_t base = ((size_t)f * MPTS + m) * 3;
        g_idx[base] = j0[k]; g_idx[base + 1] = j1[k]; g_idx[base + 2] = j2[k];
        g_w[base] = w0 * inv; g_w[base + 1] = w1 * inv; g_w[base + 2] = w2 * inv;
    }
}

// ======== GEMM A (gemmZ / gemmB): CTA 32(M) x 128(N), 8 warps 1x8, warp tile 32x16 ========
// A [k][m] via cp.async + smem split transform; B fp16 weights via cp.async.
// acc = 16 regs/thread -> 4 CTAs/SM spill-free.
// FUSE 1: epilogue combine gather(Z)+stats1 -> y1
#define A0_ABF  2560      // fp16 A buf: 32k x 80B
#define A0_AFB  4608      // fp32 A buf: 32k x 144B
#define A0_AL   (2 * A0_ABF)
#define A0_AF   (4 * A0_ABF)
#define A0_BH   (A0_AF + 2 * A0_AFB)     // 19456
#define SMEM_A0 (A0_BH + 2 * 8704)       // 36864

template <int K, int FUSE, int MTOT>
__device__ __forceinline__ void gemm_mma0(const float* __restrict__ Aall,
                                          const __half* __restrict__ Ball,
                                          float* __restrict__ Call) {
    extern __shared__ char sm[];
    const uint32_t sbase = smem_u32(sm);
    constexpr int NC = K / 32;

    const int tid = threadIdx.x;
    const int l   = tid & 31;
    const int wn  = tid >> 5;        // 0..7
    const int f   = blockIdx.z, t = f & 3;
    const int bm  = blockIdx.y * 32;
    const int bn0 = blockIdx.x * 128;
    const float* A = Aall + (size_t)f * MTOT * K;
    float*       C = Call + (size_t)f * MTOT * 256;

    const uint32_t aoff = (uint32_t)(((l & 7) + ((l >> 4) & 1) * 8) * 80 + ((l >> 3) & 1) * 16);
    const uint32_t boff = (uint32_t)((((l & 7) + ((l >> 3) & 1) * 8) * 136 +
                                      (l >> 4) * 8 + wn * 16) * 2);

    float acc[2][2][4];
    #pragma unroll
    for (int i = 0; i < 2; i++)
        #pragma unroll
        for (int j = 0; j < 2; j++)
            #pragma unroll
            for (int k = 0; k < 4; k++) acc[i][j][k] = 0.f;

    auto issueB = [&](int kc, int bb) {
        int r  = tid >> 3;
        int ce = (tid & 7) * 16;
        const __half* sh = Ball + (size_t)(kc * 32 + r) * 256 + bn0 + ce;
        uint32_t dh = sbase + A0_BH + bb * 8704 + (uint32_t)(r * 272 + ce * 2);
        CP_ASYNC16(dh,      sh);
        CP_ASYNC16(dh + 16, sh + 8);
    };
    auto issueAf = [&](int kc, int fb) {
        int r  = tid >> 3;
        int c4 = (tid & 7) * 4;
        const float* s = A + (size_t)(kc * 32 + r) * MTOT + bm + c4;
        uint32_t dd = sbase + A0_AF + fb * A0_AFB + (uint32_t)(r * 144 + c4 * 4);
        CP_ASYNC16(dd, s);
    };
    auto transform = [&](int fb, int ab) {
        int r = tid >> 3;
        int c = (tid & 7) * 4;
        uint32_t srcb = (uint32_t)(A0_AF + fb * A0_AFB + r * 144 + c * 4);
        float4 v = *(const float4*)(sm + srcb);
        uint32_t h0, l0, h1, l1;
        split2(v.x, v.y, h0, l0); split2(v.z, v.w, h1, l1);
        uint32_t dst = (uint32_t)(ab * A0_ABF + r * 80 + c * 2);
        *(uint2*)(sm + dst)         = make_uint2(h0, h1);
        *(uint2*)(sm + A0_AL + dst) = make_uint2(l0, l1);
    };
    auto compute = [&](int buf) {
        #pragma unroll
        for (int ks = 0; ks < 2; ks++) {
            uint32_t bh[4];
            LDMX4T(bh, sbase + A0_BH + buf * 8704 + boff + ks * 4352);
            #pragma unroll
            for (int mi = 0; mi < 2; mi++) {
                uint32_t ah[4], al[4];
                uint32_t ad = sbase + buf * A0_ABF + aoff + mi * 32 + ks * 1280;
                LDMX4T(ah, ad);
                LDMX4T(al, ad + A0_AL);
                MMA_F16(acc[mi][0], ah, bh[0], bh[1]);
                MMA_F16(acc[mi][1], ah, bh[2], bh[3]);
                MMA_F16(acc[mi][0], al, bh[0], bh[1]);
                MMA_F16(acc[mi][1], al, bh[2], bh[3]);
            }
        }
    };

    issueAf(0, 0); CP_COMMIT();
    issueB(0, 0); issueAf(1, 1); CP_COMMIT();
    CP_WAIT1();
    __syncthreads();
    transform(0, 0);
    for (int kc = 0; kc < NC; kc++) {
        CP_WAIT0();
        __syncthreads();
        if (kc + 1 < NC) {
            transform((kc + 1) & 1, (kc + 1) & 1);
            issueB(kc + 1, (kc + 1) & 1);
            if (kc + 2 < NC) issueAf(kc + 2, kc & 1);
            CP_COMMIT();
        }
        compute(kc & 1);
    }

    if (FUSE == 1) {
        __syncthreads();
        float* smf = (float*)sm;
        #pragma unroll
        for (int ni = 0; ni < 2; ni++) {
            int c = wn * 16 + ni * 8 + (l & 3) * 2;
            #pragma unroll
            for (int mi = 0; mi < 2; mi++) {
                int r = mi * 16 + (l >> 2);
                *(float2*)&smf[r * 136 + c]       = make_float2(acc[mi][ni][0], acc[mi][ni][1]);
                *(float2*)&smf[(r + 8) * 136 + c] = make_float2(acc[mi][ni][2], acc[mi][ni][3]);
            }
        }
        __syncthreads();
        const int oc = tid & 127, half = tid >> 7;
        const int o  = bn0 + oc;
        const float* Z = g_ZT + (size_t)f * NPTS * 256;
        float s = 0.f, q = 0.f;
        #pragma unroll 4
        for (int rr = 0; rr < 16; rr++) {
            int r = half * 16 + rr;
            int m = bm + r;
            size_t ib = ((size_t)f * MPTS + m) * 3;
            int   i0 = g_idx[ib], i1 = g_idx[ib + 1], i2 = g_idx[ib + 2];
            float w0 = g_w[ib],   w1 = g_w[ib + 1],   w2 = g_w[ib + 2];
            float v = smf[r * 136 + oc];
            v = fmaf(w0, Z[(size_t)i0 * 256 + o], v);
            v = fmaf(w1, Z[(size_t)i1 * 256 + o], v);
            v = fmaf(w2, Z[(size_t)i2 * 256 + o], v);
            g_y1[((size_t)f * MPTS + m) * 256 + o] = v;
            s += v; q = fmaf(v, v, q);
        }
        atomicAdd(&g_sum1[t * 256 + o], s);
        atomicAdd(&g_sq1 [t * 256 + o], q);
    } else {
        #pragma unroll
        for (int ni = 0; ni < 2; ni++) {
            int col = bn0 + wn * 16 + ni * 8 + (l & 3) * 2;
            #pragma unroll
            for (int mi = 0; mi < 2; mi++) {
                int row = bm + mi * 16 + (l >> 2);
                float* cp = C + (size_t)row * 256 + col;
                *(float2*)cp          = make_float2(acc[mi][ni][0], acc[mi][ni][1]);
                *(float2*)(cp + 2048) = make_float2(acc[mi][ni][2], acc[mi][ni][3]);
            }
        }
    }
}

__global__ void __launch_bounds__(256, 4) gemmZ_mma(const float* __restrict__ feats) {
    gemm_mma0<CIN, 0, NPTS>(feats, g_W1a, g_ZT);
}
__global__ void __launch_bounds__(256, 4) gemmB_mma(const float* __restrict__ ofeat) {
    gemm_mma0<CORIG, 1, MPTS>(ofeat, g_W1b, g_y1);
}

// ======== GEMM 2: CTA 32(M) x 128(N), 8 warps 1x8, warp tile 32x16, occ 4 ========
// A [m][k] register prefetch (1 float4/thread) + fused BN1+ReLU; B fp16 cp.async;
// stats2 fused. acc = 16 regs -> spill-free at occ 4.
#define G2_ABF  2560      // fp16 A buf: 32 rows x 80B
#define G2_AL   (2 * G2_ABF)
#define G2_BH   (4 * G2_ABF)             // 10240
#define G2_SC   (G2_BH + 2 * 8704)       // 27648
#define SMEM_A1 (G2_SC + 2048)           // 29696

__global__ void __launch_bounds__(256, 4) gemm2_mma() {
    extern __shared__ char sm[];
    const uint32_t sbase = smem_u32(sm);
    constexpr int K = P1, NC = K / 32;

    const int tid = threadIdx.x;
    const int l   = tid & 31;
    const int wn  = tid >> 5;       // 0..7
    const int f   = blockIdx.z, t = f & 3;
    const int bm  = blockIdx.y * 32;
    const int bn0 = blockIdx.x * 128;
    const float* A = g_y1 + (size_t)f * MPTS * K;
    float*       C = g_y2 + (size_t)f * MPTS * 256;

    float* s_sc = (float*)(sm + G2_SC);
    float* s_bi = (float*)(sm + G2_SC + 1024);
    s_sc[tid] = g_a1[t * 256 + tid];
    s_bi[tid] = g_b1[t * 256 + tid];
    __syncthreads();

    // A row-major ldmatrix (non-trans): rows l&15, col-half l>>4
    const uint32_t aoff = (uint32_t)((l & 15) * 80 + (l >> 4) * 16);
    const uint32_t boff = (uint32_t)((((l & 7) + ((l >> 3) & 1) * 8) * 136 +
                                      (l >> 4) * 8 + wn * 16) * 2);

    float acc[2][2][4];
    #pragma unroll
    for (int i = 0; i < 2; i++)
        #pragma unroll
        for (int j = 0; j < 2; j++)
            #pragma unroll
            for (int k = 0; k < 4; k++) acc[i][j][k] = 0.f;

    float4 ra;   // A prefetch: 1 float4/thread (32 rows x 32 cols per chunk)

    auto issueB = [&](int kc, int bb) {
        int r  = tid >> 3;
        int ce = (tid & 7) * 16;
        const __half* sh = g_W2 + (size_t)(kc * 32 + r) * 256 + bn0 + ce;
        uint32_t dh = sbase + G2_BH + bb * 8704 + (uint32_t)(r * 272 + ce * 2);
        CP_ASYNC16(dh,      sh);
        CP_ASYNC16(dh + 16, sh + 8);
    };
    auto loadA = [&](int kc) {
        const float* ap = A + (size_t)(bm + (tid >> 3)) * K + kc * 32 + (tid & 7) * 4;
        ra = *(const float4*)ap;
    };
    auto storeA = [&](int buf, int kc) {
        float4 v = ra;
        int cc = kc * 32 + (tid & 7) * 4;
        v.x = fmaxf(0.f, fmaf(s_sc[cc + 0], v.x, s_bi[cc + 0]));
        v.y = fmaxf(0.f, fmaf(s_sc[cc + 1], v.y, s_bi[cc + 1]));
        v.z = fmaxf(0.f, fmaf(s_sc[cc + 2], v.z, s_bi[cc + 2]));
        v.w = fmaxf(0.f, fmaf(s_sc[cc + 3], v.w, s_bi[cc + 3]));
        uint32_t h0, l0, h1, l1;
        split2(v.x, v.y, h0, l0); split2(v.z, v.w, h1, l1);
        uint32_t ao = (uint32_t)(buf * G2_ABF + (tid >> 3) * 80 + (tid & 7) * 8);
        *(uint2*)(sm + ao)         = make_uint2(h0, h1);
        *(uint2*)(sm + G2_AL + ao) = make_uint2(l0, l1);
    };
    auto compute = [&](int buf) {
        #pragma unroll
        for (int ks = 0; ks < 2; ks++) {
            uint32_t bh[4];
            LDMX4T(bh, sbase + G2_BH + buf * 8704 + boff + ks * 4352);
            #pragma unroll
            for (int mi = 0; mi < 2; mi++) {
                uint32_t ah[4], al[4];
                uint32_t ad = sbase + buf * G2_ABF + aoff + mi * 1280 + ks * 32;
                LDMX4(ah, ad);
                LDMX4(al, ad + G2_AL);
                MMA_F16(acc[mi][0], ah, bh[0], bh[1]);
                MMA_F16(acc[mi][1], ah, bh[2], bh[3]);
                MMA_F16(acc[mi][0], al, bh[0], bh[1]);
                MMA_F16(acc[mi][1], al, bh[2], bh[3]);
            }
        }
    };

    issueB(0, 0); CP_COMMIT();
    loadA(0); storeA(0, 0);
    CP_WAIT0();
    __syncthreads();
    for (int kc = 0; kc < NC; kc++) {
        if (kc + 1 < NC) {
            issueB(kc + 1, (kc + 1) & 1); CP_COMMIT();
            loadA(kc + 1);
        }
        compute(kc & 1);
        if (kc + 1 < NC) {
            storeA((kc + 1) & 1, kc + 1);
            CP_WAIT0();
            __syncthreads();
        }
    }

    // epilogue: store + fused stats2
    #pragma unroll
    for (int ni = 0; ni < 2; ni++) {
        int col = bn0 + wn * 16 + ni * 8 + (l & 3) * 2;
        float s0 = 0.f, q0 = 0.f, s1 = 0.f, q1 = 0.f;
        #pragma unroll
        for (int mi = 0; mi < 2; mi++) {
            int row = bm + mi * 16 + (l >> 2);
            float v0 = acc[mi][ni][0], v1 = acc[mi][ni][1];
            float v2 = acc[mi][ni][2], v3 = acc[mi][ni][3];
            float* cp = C + (size_t)row * 256 + col;
            *(float2*)cp          = make_float2(v0, v1);
            *(float2*)(cp + 2048) = make_float2(v2, v3);
            s0 += v0 + v2; s1 += v1 + v3;
            q0 += fmaf(v0, v0, v2 * v2);
            q1 += fmaf(v1, v1, v3 * v3);
        }
        #pragma unroll
        for (int d = 4; d < 32; d <<= 1) {
            s0 += __shfl_xor_sync(0xffffffffu, s0, d);
            s1 += __shfl_xor_sync(0xffffffffu, s1, d);
            q0 += __shfl_xor_sync(0xffffffffu, q0, d);
            q1 += __shfl_xor_sync(0xffffffffu, q1, d);
        }
        if (l < 4) {
            atomicAdd(&g_sum2[t * 256 + col],     s0);
            atomicAdd(&g_sum2[t * 256 + col + 1], s1);
            atomicAdd(&g_sq2 [t * 256 + col],     q0);
            atomicAdd(&g_sq2 [t * 256 + col + 1], q1);
        }
    }
}

// ---------------- finalize BN coefficients ----------------
__global__ void finalize_kernel(int which, const float* __restrict__ gamma,
                                const float* __restrict__ beta) {
    int i = blockIdx.x * 256 + threadIdx.x;
    if (i >= TT * P1) return;
    const float rcnt = 1.0f / (float)(BB * MPTS);
    float sum = (which == 1) ? g_sum1[i] : g_sum2[i];
    float sq  = (which == 1) ? g_sq1[i]  : g_sq2[i];
    float mean = sum * rcnt;
    float var  = fmaf(-mean, mean, sq * rcnt);
    int o = i & 255;
    float a = gamma[o] * rsqrtf(var + EPS_BN);
    float b = fmaf(-mean, a, beta[o]);
    if (which == 1) { g_a1[i] = a; g_b1[i] = b; }
    else            { g_a2[i] = a; g_b2[i] = b; }
}

// ---------------- output: BN2+ReLU + transpose [f][m][o] -> [f][o][m] ----------------
__global__ void output_kernel(float* __restrict__ out) {
    __shared__ float tile[32][33];
    int f = blockIdx.z, t = f & 3;
    int m0 = blockIdx.x * 32, o0 = blockIdx.y * 32;
    int tx = threadIdx.x, ty = threadIdx.y;
    #pragma unroll
    for (int i = ty; i < 32; i += 8) {
        int o = o0 + tx;
        float v = g_y2[((size_t)f * MPTS + m0 + i) * P2 + o];
        tile[i][tx] = fmaxf(0.f, fmaf(g_a2[t * P2 + o], v, g_b2[t * P2 + o]));
    }
    __syncthreads();
    #pragma unroll
    for (int i = ty; i < 32; i += 8)
        out[((size_t)f * P2 + o0 + i) * MPTS + m0 + tx] = tile[tx][i];
}

// ---------------- launch ----------------
extern "C" void kernel_launch(void* const* d_in, const int* in_sizes, int n_in,
                              void* d_out, int out_size) {
    const float* xyzs   = (const float*)d_in[0];
    const float* oxyzs  = (const float*)d_in[1];
    const float* feats  = (const float*)d_in[2];
    const float* ofeat  = (const float*)d_in[3];
    const float* W1     = (const float*)d_in[4];
    const float* gamma1 = (const float*)d_in[5];
    const float* beta1  = (const float*)d_in[6];
    const float* W2     = (const float*)d_in[7];
    const float* gamma2 = (const float*)d_in[8];
    const float* beta2  = (const float*)d_in[9];
    float* out = (float*)d_out;

    (void)cudaFuncSetAttribute(gemmZ_mma, cudaFuncAttributeMaxDynamicSharedMemorySize, SMEM_A0);
    (void)cudaFuncSetAttribute(gemmB_mma, cudaFuncAttributeMaxDynamicSharedMemorySize, SMEM_A0);
    (void)cudaFuncSetAttribute(gemm2_mma, cudaFuncAttributeMaxDynamicSharedMemorySize, SMEM_A1);

    const int xyz_elems = FRAMES * MPTS * 3;
    const int x_elems   = FRAMES * P2 * MPTS;
    float* out_x = out;
    if (out_size >= xyz_elems + x_elems) {
        cudaMemcpyAsync(out, oxyzs, (size_t)xyz_elems * sizeof(float),
                        cudaMemcpyDeviceToDevice, 0);
        out_x = out + xyz_elems;
    }

    prep_kernel<<<384, 256>>>(W1, W2);
    knn_kernel<<<dim3(MPTS / 1024, FRAMES), 256>>>(xyzs, oxyzs);

    gemmZ_mma<<<dim3(2, NPTS / 32, FRAMES), 256, SMEM_A0>>>(feats);   // Z = feats^T @ W1a
    gemmB_mma<<<dim3(2, MPTS / 32, FRAMES), 256, SMEM_A0>>>(ofeat);   // y1 + gather(Z); stats1
    finalize_kernel<<<4, 256>>>(1, gamma1, beta1);

    gemm2_mma<<<dim3(2, MPTS / 32, FRAMES), 256, SMEM_A1>>>();        // y2 = relu(bn1(y1)) @ W2; stats2
    finalize_kernel<<<4, 256>>>(2, gamma2, beta2);

    output_kernel<<<dim3(MPTS / 32, P2 / 32, FRAMES), dim3(32, 8)>>>(out_x);
}

// round 15
// speedup vs baseline: 1.0921x; 1.0921x over previous
#include <cuda_runtime.h>
#include <cuda_fp16.h>
#include <stdint.h>
#include <math.h>

// ---------------- problem constants ----------------
#define BB      8
#define TT      4
#define NPTS    1024
#define MPTS    4096
#define CIN     256
#define CORIG   128
#define CCAT    384
#define P1      256
#define P2      256
#define FRAMES  32          // B*T
#define EPS_D   1e-8f
#define EPS_BN  1e-5f

// ---------------- scratch (device globals, no runtime alloc) ----------------
__device__ __align__(16) int   g_idx[FRAMES * MPTS * 3];
__device__ __align__(16) float g_w  [FRAMES * MPTS * 3];
__device__ __align__(16) float g_ZT [(size_t)FRAMES * NPTS * P1];     // [f][n][o]
__device__ __align__(16) float g_y1 [(size_t)FRAMES * MPTS * P1];     // [f][m][o]
__device__ __align__(16) float g_y2 [(size_t)FRAMES * MPTS * P2];     // [f][m][o]
// fp16 weights, [k][n] layout (n contiguous)
__device__ __align__(16) __half g_W1a[CIN * P1];
__device__ __align__(16) __half g_W1b[CORIG * P1];
__device__ __align__(16) __half g_W2 [P1 * P2];
__device__ float g_sum1[TT * P1], g_sq1[TT * P1], g_a1[TT * P1], g_b1[TT * P1];
__device__ float g_sum2[TT * P2], g_sq2[TT * P2], g_a2[TT * P2], g_b2[TT * P2];

// ---------------- helpers ----------------
__device__ __forceinline__ uint32_t smem_u32(const void* p) {
    uint32_t a;
    asm("{ .reg .u64 t; cvta.to.shared.u64 t, %1; cvt.u32.u64 %0, t; }" : "=r"(a) : "l"(p));
    return a;
}

#define LDMX4(r, addr) \
    asm volatile("ldmatrix.sync.aligned.m8n8.x4.shared.b16 {%0,%1,%2,%3}, [%4];" \
        : "=r"((r)[0]), "=r"((r)[1]), "=r"((r)[2]), "=r"((r)[3]) : "r"(addr))

#define LDMX4T(r, addr) \
    asm volatile("ldmatrix.sync.aligned.m8n8.x4.trans.shared.b16 {%0,%1,%2,%3}, [%4];" \
        : "=r"((r)[0]), "=r"((r)[1]), "=r"((r)[2]), "=r"((r)[3]) : "r"(addr))

#define MMA_F16(d, a, b0, b1) \
    asm volatile("mma.sync.aligned.m16n8k16.row.col.f32.f16.f16.f32 " \
        "{%0,%1,%2,%3},{%4,%5,%6,%7},{%8,%9},{%0,%1,%2,%3};" \
        : "+f"((d)[0]), "+f"((d)[1]), "+f"((d)[2]), "+f"((d)[3]) \
        : "r"((a)[0]), "r"((a)[1]), "r"((a)[2]), "r"((a)[3]), "r"(b0), "r"(b1))

#define CP_ASYNC16(dst, src) \
    asm volatile("cp.async.cg.shared.global [%0], [%1], 16;" :: "r"(dst), "l"(src))
#define CP_COMMIT()  asm volatile("cp.async.commit_group;" ::: "memory")
#define CP_WAIT0()   asm volatile("cp.async.wait_group 0;" ::: "memory")
#define CP_WAIT1()   asm volatile("cp.async.wait_group 1;" ::: "memory")

// fp16 hi/lo split of two floats
__device__ __forceinline__ void split2(float a, float b, uint32_t& h, uint32_t& l) {
    __half2 hb = __floats2half2_rn(a, b);
    float2 hf = __half22float2(hb);
    __half2 lb = __floats2half2_rn(a - hf.x, b - hf.y);
    h = *reinterpret_cast<uint32_t*>(&hb);
    l = *reinterpret_cast<uint32_t*>(&lb);
}

// ---------------- prep ----------------
__global__ void prep_kernel(const float* __restrict__ W1, const float* __restrict__ W2) {
    int i = blockIdx.x * 256 + threadIdx.x;
    if (i < TT * P1) { g_sum1[i] = 0.f; g_sq1[i] = 0.f; g_sum2[i] = 0.f; g_sq2[i] = 0.f; }
    if (i < P1 * CCAT) {
        int o = i / CCAT, c = i % CCAT;
        __half h = __float2half_rn(W1[i]);
        if (c < CIN) g_W1a[c * P1 + o] = h;
        else         g_W1b[(c - CIN) * P1 + o] = h;
    }
    if (i < P2 * P1) {
        int o = i / P1, c = i % P1;
        g_W2[c * P2 + o] = __float2half_rn(W2[i]);
    }
}

// ---------------- three_nn: 2 m-points per thread (known-good R13 version) ----------------
__global__ void knn_kernel(const float* __restrict__ xyzs, const float* __restrict__ oxyzs) {
    __shared__ float sx[NPTS], sy[NPTS], sz[NPTS];
    int f = blockIdx.y;
    const float* p = xyzs + (size_t)f * NPTS * 3;
    for (int i = threadIdx.x; i < NPTS; i += 256) {
        sx[i] = p[3 * i]; sy[i] = p[3 * i + 1]; sz[i] = p[3 * i + 2];
    }
    __syncthreads();
    int m1 = blockIdx.x * 256 + threadIdx.x;
    int m2 = m1 + 2048;
    const float* q1 = oxyzs + ((size_t)f * MPTS + m1) * 3;
    const float* q2 = oxyzs + ((size_t)f * MPTS + m2) * 3;
    float ax = q1[0], ay = q1[1], az = q1[2];
    float cx = q2[0], cy = q2[1], cz = q2[2];
    float p0 = 1e30f, p1_ = 1e30f, p2_ = 1e30f;
    int   pi0 = 0,    pi1 = 0,    pi2 = 0;
    float r0 = 1e30f, r1 = 1e30f, r2 = 1e30f;
    int   ri0 = 0,    ri1 = 0,    ri2 = 0;
    #pragma unroll 4
    for (int n = 0; n < NPTS; n++) {
        float x = sx[n], y = sy[n], z = sz[n];
        float dx = ax - x, dy = ay - y, dz = az - z;
        float d = fmaf(dx, dx, fmaf(dy, dy, dz * dz));
        if (d < p2_) {
            if (d < p1_) {
                p2_ = p1_; pi2 = pi1;
                if (d < p0) { p1_ = p0; pi1 = pi0; p0 = d; pi0 = n; }
                else        { p1_ = d;  pi1 = n; }
            } else { p2_ = d; pi2 = n; }
        }
        float ex = cx - x, ey = cy - y, ez = cz - z;
        float e = fmaf(ex, ex, fmaf(ey, ey, ez * ez));
        if (e < r2) {
            if (e < r1) {
                r2 = r1; ri2 = ri1;
                if (e < r0) { r1 = r0; ri1 = ri0; r0 = e; ri0 = n; }
                else        { r1 = e;  ri1 = n; }
            } else { r2 = e; ri2 = n; }
        }
    }
    {
        float w0 = 1.f / (p0 + EPS_D), w1 = 1.f / (p1_ + EPS_D), w2 = 1.f / (p2_ + EPS_D);
        float inv = 1.f / (w0 + w1 + w2);
        size_t base = ((size_t)f * MPTS + m1) * 3;
        g_idx[base] = pi0; g_idx[base + 1] = pi1; g_idx[base + 2] = pi2;
        g_w[base] = w0 * inv; g_w[base + 1] = w1 * inv; g_w[base + 2] = w2 * inv;
    }
    {
        float w0 = 1.f / (r0 + EPS_D), w1 = 1.f / (r1 + EPS_D), w2 = 1.f / (r2 + EPS_D);
        float inv = 1.f / (w0 + w1 + w2);
        size_t base = ((size_t)f * MPTS + m2) * 3;
        g_idx[base] = ri0; g_idx[base + 1] = ri1; g_idx[base + 2] = ri2;
        g_w[base] = w0 * inv; g_w[base + 1] = w1 * inv; g_w[base + 2] = w2 * inv;
    }
}

// ======== GEMM A (gemmZ / gemmB): CTA 32(M) x 128(N), 8 warps 1x8, warp tile 32x16 ========
// A [k][m] via cp.async + smem split transform; B fp16 weights via cp.async.
// acc = 16 regs/thread -> 4 CTAs/SM spill-free. (R13-validated)
#define A0_ABF  2560      // fp16 A buf: 32k x 80B
#define A0_AFB  4608      // fp32 A buf: 32k x 144B
#define A0_AL   (2 * A0_ABF)
#define A0_AF   (4 * A0_ABF)
#define A0_BH   (A0_AF + 2 * A0_AFB)     // 19456
#define SMEM_A0 (A0_BH + 2 * 8704)       // 36864

template <int K, int FUSE, int MTOT>
__device__ __forceinline__ void gemm_mma0(const float* __restrict__ Aall,
                                          const __half* __restrict__ Ball,
                                          float* __restrict__ Call) {
    extern __shared__ char sm[];
    const uint32_t sbase = smem_u32(sm);
    constexpr int NC = K / 32;

    const int tid = threadIdx.x;
    const int l   = tid & 31;
    const int wn  = tid >> 5;        // 0..7
    const int f   = blockIdx.z, t = f & 3;
    const int bm  = blockIdx.y * 32;
    const int bn0 = blockIdx.x * 128;
    const float* A = Aall + (size_t)f * MTOT * K;
    float*       C = Call + (size_t)f * MTOT * 256;

    const uint32_t aoff = (uint32_t)(((l & 7) + ((l >> 4) & 1) * 8) * 80 + ((l >> 3) & 1) * 16);
    const uint32_t boff = (uint32_t)((((l & 7) + ((l >> 3) & 1) * 8) * 136 +
                                      (l >> 4) * 8 + wn * 16) * 2);

    float acc[2][2][4];
    #pragma unroll
    for (int i = 0; i < 2; i++)
        #pragma unroll
        for (int j = 0; j < 2; j++)
            #pragma unroll
            for (int k = 0; k < 4; k++) acc[i][j][k] = 0.f;

    auto issueB = [&](int kc, int bb) {
        int r  = tid >> 3;
        int ce = (tid & 7) * 16;
        const __half* sh = Ball + (size_t)(kc * 32 + r) * 256 + bn0 + ce;
        uint32_t dh = sbase + A0_BH + bb * 8704 + (uint32_t)(r * 272 + ce * 2);
        CP_ASYNC16(dh,      sh);
        CP_ASYNC16(dh + 16, sh + 8);
    };
    auto issueAf = [&](int kc, int fb) {
        int r  = tid >> 3;
        int c4 = (tid & 7) * 4;
        const float* s = A + (size_t)(kc * 32 + r) * MTOT + bm + c4;
        uint32_t dd = sbase + A0_AF + fb * A0_AFB + (uint32_t)(r * 144 + c4 * 4);
        CP_ASYNC16(dd, s);
    };
    auto transform = [&](int fb, int ab) {
        int r = tid >> 3;
        int c = (tid & 7) * 4;
        uint32_t srcb = (uint32_t)(A0_AF + fb * A0_AFB + r * 144 + c * 4);
        float4 v = *(const float4*)(sm + srcb);
        uint32_t h0, l0, h1, l1;
        split2(v.x, v.y, h0, l0); split2(v.z, v.w, h1, l1);
        uint32_t dst = (uint32_t)(ab * A0_ABF + r * 80 + c * 2);
        *(uint2*)(sm + dst)         = make_uint2(h0, h1);
        *(uint2*)(sm + A0_AL + dst) = make_uint2(l0, l1);
    };
    auto compute = [&](int buf) {
        #pragma unroll
        for (int ks = 0; ks < 2; ks++) {
            uint32_t bh[4];
            LDMX4T(bh, sbase + A0_BH + buf * 8704 + boff + ks * 4352);
            #pragma unroll
            for (int mi = 0; mi < 2; mi++) {
                uint32_t ah[4], al[4];
                uint32_t ad = sbase + buf * A0_ABF + aoff + mi * 32 + ks * 1280;
                LDMX4T(ah, ad);
                LDMX4T(al, ad + A0_AL);
                MMA_F16(acc[mi][0], ah, bh[0], bh[1]);
                MMA_F16(acc[mi][1], ah, bh[2], bh[3]);
                MMA_F16(acc[mi][0], al, bh[0], bh[1]);
                MMA_F16(acc[mi][1], al, bh[2], bh[3]);
            }
        }
    };

    issueAf(0, 0); CP_COMMIT();
    issueB(0, 0); issueAf(1, 1); CP_COMMIT();
    CP_WAIT1();
    __syncthreads();
    transform(0, 0);
    for (int kc = 0; kc < NC; kc++) {
        CP_WAIT0();
        __syncthreads();
        if (kc + 1 < NC) {
            transform((kc + 1) & 1, (kc + 1) & 1);
            issueB(kc + 1, (kc + 1) & 1);
            if (kc + 2 < NC) issueAf(kc + 2, kc & 1);
            CP_COMMIT();
        }
        compute(kc & 1);
    }

    if (FUSE == 1) {
        __syncthreads();
        float* smf = (float*)sm;
        #pragma unroll
        for (int ni = 0; ni < 2; ni++) {
            int c = wn * 16 + ni * 8 + (l & 3) * 2;
            #pragma unroll
            for (int mi = 0; mi < 2; mi++) {
                int r = mi * 16 + (l >> 2);
                *(float2*)&smf[r * 136 + c]       = make_float2(acc[mi][ni][0], acc[mi][ni][1]);
                *(float2*)&smf[(r + 8) * 136 + c] = make_float2(acc[mi][ni][2], acc[mi][ni][3]);
            }
        }
        __syncthreads();
        const int oc = tid & 127, half = tid >> 7;
        const int o  = bn0 + oc;
        const float* Z = g_ZT + (size_t)f * NPTS * 256;
        float s = 0.f, q = 0.f;
        #pragma unroll 4
        for (int rr = 0; rr < 16; rr++) {
            int r = half * 16 + rr;
            int m = bm + r;
            size_t ib = ((size_t)f * MPTS + m) * 3;
            int   i0 = g_idx[ib], i1 = g_idx[ib + 1], i2 = g_idx[ib + 2];
            float w0 = g_w[ib],   w1 = g_w[ib + 1],   w2 = g_w[ib + 2];
            float v = smf[r * 136 + oc];
            v = fmaf(w0, Z[(size_t)i0 * 256 + o], v);
            v = fmaf(w1, Z[(size_t)i1 * 256 + o], v);
            v = fmaf(w2, Z[(size_t)i2 * 256 + o], v);
            g_y1[((size_t)f * MPTS + m) * 256 + o] = v;
            s += v; q = fmaf(v, v, q);
        }
        atomicAdd(&g_sum1[t * 256 + o], s);
        atomicAdd(&g_sq1 [t * 256 + o], q);
    } else {
        #pragma unroll
        for (int ni = 0; ni < 2; ni++) {
            int col = bn0 + wn * 16 + ni * 8 + (l & 3) * 2;
            #pragma unroll
            for (int mi = 0; mi < 2; mi++) {
                int row = bm + mi * 16 + (l >> 2);
                float* cp = C + (size_t)row * 256 + col;
                *(float2*)cp          = make_float2(acc[mi][ni][0], acc[mi][ni][1]);
                *(float2*)(cp + 2048) = make_float2(acc[mi][ni][2], acc[mi][ni][3]);
            }
        }
    }
}

__global__ void __launch_bounds__(256, 4) gemmZ_mma(const float* __restrict__ feats) {
    gemm_mma0<CIN, 0, NPTS>(feats, g_W1a, g_ZT);
}
__global__ void __launch_bounds__(256, 4) gemmB_mma(const float* __restrict__ ofeat) {
    gemm_mma0<CORIG, 1, MPTS>(ofeat, g_W1b, g_y1);
}

// ======== GEMM 2: CTA 32(M) x 128(N), 8 warps 1x8, warp tile 32x16, occ 4 ========
// A = y1 [m][k] via cp.async + smem transform (BN1+ReLU+split inside transform):
// no global latency on the barrier path (fixes R14's regression).
// B fp16 via cp.async; stats2 fused in epilogue.
#define G2_ABF  2560      // fp16 A buf: 32 rows x 80B
#define G2_AFB  4608      // fp32 A buf: 32 rows x 144B
#define G2_AL   (2 * G2_ABF)
#define G2_AF   (4 * G2_ABF)             // 10240
#define G2_BH   (G2_AF + 2 * G2_AFB)     // 19456
#define G2_SC   (G2_BH + 2 * 8704)       // 36864
#define SMEM_A1 (G2_SC + 2048)           // 38912

__global__ void __launch_bounds__(256, 4) gemm2_mma() {
    extern __shared__ char sm[];
    const uint32_t sbase = smem_u32(sm);
    constexpr int K = P1, NC = K / 32;

    const int tid = threadIdx.x;
    const int l   = tid & 31;
    const int wn  = tid >> 5;       // 0..7
    const int f   = blockIdx.z, t = f & 3;
    const int bm  = blockIdx.y * 32;
    const int bn0 = blockIdx.x * 128;
    const float* A = g_y1 + (size_t)f * MPTS * K;
    float*       C = g_y2 + (size_t)f * MPTS * 256;

    float* s_sc = (float*)(sm + G2_SC);
    float* s_bi = (float*)(sm + G2_SC + 1024);
    s_sc[tid] = g_a1[t * 256 + tid];
    s_bi[tid] = g_b1[t * 256 + tid];
    // visibility before first transform is covered by the prologue __syncthreads()

    // A row-major ldmatrix (non-trans): rows l&15, k-half l>>4
    const uint32_t aoff = (uint32_t)((l & 15) * 80 + (l >> 4) * 16);
    const uint32_t boff = (uint32_t)((((l & 7) + ((l >> 3) & 1) * 8) * 136 +
                                      (l >> 4) * 8 + wn * 16) * 2);

    float acc[2][2][4];
    #pragma unroll
    for (int i = 0; i < 2; i++)
        #pragma unroll
        for (int j = 0; j < 2; j++)
            #pragma unroll
            for (int k = 0; k < 4; k++) acc[i][j][k] = 0.f;

    auto issueB = [&](int kc, int bb) {
        int r  = tid >> 3;
        int ce = (tid & 7) * 16;
        const __half* sh = g_W2 + (size_t)(kc * 32 + r) * 256 + bn0 + ce;
        uint32_t dh = sbase + G2_BH + bb * 8704 + (uint32_t)(r * 272 + ce * 2);
        CP_ASYNC16(dh,      sh);
        CP_ASYNC16(dh + 16, sh + 8);
    };
    auto issueAf = [&](int kc, int fb) {
        int r  = tid >> 3;                 // m row 0..31
        int c4 = (tid & 7) * 4;            // k col
        const float* s = A + (size_t)(bm + r) * K + kc * 32 + c4;
        uint32_t dd = sbase + G2_AF + fb * G2_AFB + (uint32_t)(r * 144 + c4 * 4);
        CP_ASYNC16(dd, s);
    };
    auto transform = [&](int kc, int fb, int ab) {
        int r = tid >> 3;
        int c = (tid & 7) * 4;
        uint32_t srcb = (uint32_t)(G2_AF + fb * G2_AFB + r * 144 + c * 4);
        float4 v = *(const float4*)(sm + srcb);
        int cc = kc * 32 + c;
        v.x = fmaxf(0.f, fmaf(s_sc[cc + 0], v.x, s_bi[cc + 0]));
        v.y = fmaxf(0.f, fmaf(s_sc[cc + 1], v.y, s_bi[cc + 1]));
        v.z = fmaxf(0.f, fmaf(s_sc[cc + 2], v.z, s_bi[cc + 2]));
        v.w = fmaxf(0.f, fmaf(s_sc[cc + 3], v.w, s_bi[cc + 3]));
        uint32_t h0, l0, h1, l1;
        split2(v.x, v.y, h0, l0); split2(v.z, v.w, h1, l1);
        uint32_t dst = (uint32_t)(ab * G2_ABF + r * 80 + c * 2);
        *(uint2*)(sm + dst)         = make_uint2(h0, h1);
        *(uint2*)(sm + G2_AL + dst) = make_uint2(l0, l1);
    };
    auto compute = [&](int buf) {
        #pragma unroll
        for (int ks = 0; ks < 2; ks++) {
            uint32_t bh[4];
            LDMX4T(bh, sbase + G2_BH + buf * 8704 + boff + ks * 4352);
            #pragma unroll
            for (int mi = 0; mi < 2; mi++) {
                uint32_t ah[4], al[4];
                uint32_t ad = sbase + buf * G2_ABF + aoff + mi * 1280 + ks * 32;
                LDMX4(ah, ad);
                LDMX4(al, ad + G2_AL);
                MMA_F16(acc[mi][0], ah, bh[0], bh[1]);
                MMA_F16(acc[mi][1], ah, bh[2], bh[3]);
                MMA_F16(acc[mi][0], al, bh[0], bh[1]);
                MMA_F16(acc[mi][1], al, bh[2], bh[3]);
            }
        }
    };

    issueAf(0, 0); CP_COMMIT();
    issueB(0, 0); issueAf(1, 1); CP_COMMIT();
    CP_WAIT1();
    __syncthreads();                       // A(0) landed; coef table visible
    transform(0, 0, 0);
    for (int kc = 0; kc < NC; kc++) {
        CP_WAIT0();
        __syncthreads();
        if (kc + 1 < NC) {
            transform(kc + 1, (kc + 1) & 1, (kc + 1) & 1);
            issueB(kc + 1, (kc + 1) & 1);
            if (kc + 2 < NC) issueAf(kc + 2, kc & 1);
            CP_COMMIT();
        }
        compute(kc & 1);
    }

    // epilogue: store + fused stats2
    #pragma unroll
    for (int ni = 0; ni < 2; ni++) {
        int col = bn0 + wn * 16 + ni * 8 + (l & 3) * 2;
        float s0 = 0.f, q0 = 0.f, s1 = 0.f, q1 = 0.f;
        #pragma unroll
        for (int mi = 0; mi < 2; mi++) {
            int row = bm + mi * 16 + (l >> 2);
            float v0 = acc[mi][ni][0], v1 = acc[mi][ni][1];
            float v2 = acc[mi][ni][2], v3 = acc[mi][ni][3];
            float* cp = C + (size_t)row * 256 + col;
            *(float2*)cp          = make_float2(v0, v1);
            *(float2*)(cp + 2048) = make_float2(v2, v3);
            s0 += v0 + v2; s1 += v1 + v3;
            q0 += fmaf(v0, v0, v2 * v2);
            q1 += fmaf(v1, v1, v3 * v3);
        }
        #pragma unroll
        for (int d = 4; d < 32; d <<= 1) {
            s0 += __shfl_xor_sync(0xffffffffu, s0, d);
            s1 += __shfl_xor_sync(0xffffffffu, s1, d);
            q0 += __shfl_xor_sync(0xffffffffu, q0, d);
            q1 += __shfl_xor_sync(0xffffffffu, q1, d);
        }
        if (l < 4) {
            atomicAdd(&g_sum2[t * 256 + col],     s0);
            atomicAdd(&g_sum2[t * 256 + col + 1], s1);
            atomicAdd(&g_sq2 [t * 256 + col],     q0);
            atomicAdd(&g_sq2 [t * 256 + col + 1], q1);
        }
    }
}

// ---------------- finalize BN coefficients ----------------
__global__ void finalize_kernel(int which, const float* __restrict__ gamma,
                                const float* __restrict__ beta) {
    int i = blockIdx.x * 256 + threadIdx.x;
    if (i >= TT * P1) return;
    const float rcnt = 1.0f / (float)(BB * MPTS);
    float sum = (which == 1) ? g_sum1[i] : g_sum2[i];
    float sq  = (which == 1) ? g_sq1[i]  : g_sq2[i];
    float mean = sum * rcnt;
    float var  = fmaf(-mean, mean, sq * rcnt);
    int o = i & 255;
    float a = gamma[o] * rsqrtf(var + EPS_BN);
    float b = fmaf(-mean, a, beta[o]);
    if (which == 1) { g_a1[i] = a; g_b1[i] = b; }
    else            { g_a2[i] = a; g_b2[i] = b; }
}

// ---------------- output: BN2+ReLU + transpose [f][m][o] -> [f][o][m] ----------------
__global__ void output_kernel(float* __restrict__ out) {
    __shared__ float tile[32][33];
    int f = blockIdx.z, t = f & 3;
    int m0 = blockIdx.x * 32, o0 = blockIdx.y * 32;
    int tx = threadIdx.x, ty = threadIdx.y;
    #pragma unroll
    for (int i = ty; i < 32; i += 8) {
        int o = o0 + tx;
        float v = g_y2[((size_t)f * MPTS + m0 + i) * P2 + o];
        tile[i][tx] = fmaxf(0.f, fmaf(g_a2[t * P2 + o], v, g_b2[t * P2 + o]));
    }
    __syncthreads();
    #pragma unroll
    for (int i = ty; i < 32; i += 8)
        out[((size_t)f * P2 + o0 + i) * MPTS + m0 + tx] = tile[tx][i];
}

// ---------------- launch ----------------
extern "C" void kernel_launch(void* const* d_in, const int* in_sizes, int n_in,
                              void* d_out, int out_size) {
    const float* xyzs   = (const float*)d_in[0];
    const float* oxyzs  = (const float*)d_in[1];
    const float* feats  = (const float*)d_in[2];
    const float* ofeat  = (const float*)d_in[3];
    const float* W1     = (const float*)d_in[4];
    const float* gamma1 = (const float*)d_in[5];
    const float* beta1  = (const float*)d_in[6];
    const float* W2     = (const float*)d_in[7];
    const float* gamma2 = (const float*)d_in[8];
    const float* beta2  = (const float*)d_in[9];
    float* out = (float*)d_out;

    (void)cudaFuncSetAttribute(gemmZ_mma, cudaFuncAttributeMaxDynamicSharedMemorySize, SMEM_A0);
    (void)cudaFuncSetAttribute(gemmB_mma, cudaFuncAttributeMaxDynamicSharedMemorySize, SMEM_A0);
    (void)cudaFuncSetAttribute(gemm2_mma, cudaFuncAttributeMaxDynamicSharedMemorySize, SMEM_A1);

    const int xyz_elems = FRAMES * MPTS * 3;
    const int x_elems   = FRAMES * P2 * MPTS;
    float* out_x = out;
    if (out_size >= xyz_elems + x_elems) {
        cudaMemcpyAsync(out, oxyzs, (size_t)xyz_elems * sizeof(float),
                        cudaMemcpyDeviceToDevice, 0);
        out_x = out + xyz_elems;
    }

    prep_kernel<<<384, 256>>>(W1, W2);
    knn_kernel<<<dim3(MPTS / 512, FRAMES), 256>>>(xyzs, oxyzs);

    gemmZ_mma<<<dim3(2, NPTS / 32, FRAMES), 256, SMEM_A0>>>(feats);   // Z = feats^T @ W1a
    gemmB_mma<<<dim3(2, MPTS / 32, FRAMES), 256, SMEM_A0>>>(ofeat);   // y1 + gather(Z); stats1
    finalize_kernel<<<4, 256>>>(1, gamma1, beta1);

    gemm2_mma<<<dim3(2, MPTS / 32, FRAMES), 256, SMEM_A1>>>();        // y2 = relu(bn1(y1)) @ W2; stats2
    finalize_kernel<<<4, 256>>>(2, gamma2, beta2);

    output_kernel<<<dim3(MPTS / 32, P2 / 32, FRAMES), dim3(32, 8)>>>(out_x);
}

// round 16
// speedup vs baseline: 1.1580x; 1.0604x over previous
#include <cuda_runtime.h>
#include <cuda_fp16.h>
#include <stdint.h>
#include <math.h>

// ---------------- problem constants ----------------
#define BB      8
#define TT      4
#define NPTS    1024
#define MPTS    4096
#define CIN     256
#define CORIG   128
#define CCAT    384
#define P1      256
#define P2      256
#define FRAMES  32          // B*T
#define EPS_D   1e-8f
#define EPS_BN  1e-5f

// ---------------- scratch (device globals, no runtime alloc) ----------------
__device__ __align__(16) int   g_idx[FRAMES * MPTS * 3];
__device__ __align__(16) float g_w  [FRAMES * MPTS * 3];
__device__ __align__(16) float g_ZT [(size_t)FRAMES * NPTS * P1];     // [f][n][o]
__device__ __align__(16) float g_y1 [(size_t)FRAMES * MPTS * P1];     // [f][m][o]
__device__ __align__(16) float g_y2 [(size_t)FRAMES * MPTS * P2];     // [f][m][o]
// fp16 weights, [k][n] layout (n contiguous)
__device__ __align__(16) __half g_W1a[CIN * P1];
__device__ __align__(16) __half g_W1b[CORIG * P1];
__device__ __align__(16) __half g_W2 [P1 * P2];
__device__ float g_sum1[TT * P1], g_sq1[TT * P1], g_a1[TT * P1], g_b1[TT * P1];
__device__ float g_sum2[TT * P2], g_sq2[TT * P2], g_a2[TT * P2], g_b2[TT * P2];

// ---------------- helpers ----------------
__device__ __forceinline__ uint32_t smem_u32(const void* p) {
    uint32_t a;
    asm("{ .reg .u64 t; cvta.to.shared.u64 t, %1; cvt.u32.u64 %0, t; }" : "=r"(a) : "l"(p));
    return a;
}

#define LDMX4(r, addr) \
    asm volatile("ldmatrix.sync.aligned.m8n8.x4.shared.b16 {%0,%1,%2,%3}, [%4];" \
        : "=r"((r)[0]), "=r"((r)[1]), "=r"((r)[2]), "=r"((r)[3]) : "r"(addr))

#define LDMX4T(r, addr) \
    asm volatile("ldmatrix.sync.aligned.m8n8.x4.trans.shared.b16 {%0,%1,%2,%3}, [%4];" \
        : "=r"((r)[0]), "=r"((r)[1]), "=r"((r)[2]), "=r"((r)[3]) : "r"(addr))

#define MMA_F16(d, a, b0, b1) \
    asm volatile("mma.sync.aligned.m16n8k16.row.col.f32.f16.f16.f32 " \
        "{%0,%1,%2,%3},{%4,%5,%6,%7},{%8,%9},{%0,%1,%2,%3};" \
        : "+f"((d)[0]), "+f"((d)[1]), "+f"((d)[2]), "+f"((d)[3]) \
        : "r"((a)[0]), "r"((a)[1]), "r"((a)[2]), "r"((a)[3]), "r"(b0), "r"(b1))

#define CP_ASYNC16(dst, src) \
    asm volatile("cp.async.cg.shared.global [%0], [%1], 16;" :: "r"(dst), "l"(src))
#define CP_COMMIT()  asm volatile("cp.async.commit_group;" ::: "memory")
#define CP_WAIT0()   asm volatile("cp.async.wait_group 0;" ::: "memory")
#define CP_WAIT1()   asm volatile("cp.async.wait_group 1;" ::: "memory")

// fp16 hi/lo split of two floats
__device__ __forceinline__ void split2(float a, float b, uint32_t& h, uint32_t& l) {
    __half2 hb = __floats2half2_rn(a, b);
    float2 hf = __half22float2(hb);
    __half2 lb = __floats2half2_rn(a - hf.x, b - hf.y);
    h = *reinterpret_cast<uint32_t*>(&hb);
    l = *reinterpret_cast<uint32_t*>(&lb);
}

// ---------------- prep ----------------
__global__ void prep_kernel(const float* __restrict__ W1, const float* __restrict__ W2) {
    int i = blockIdx.x * 256 + threadIdx.x;
    if (i < TT * P1) { g_sum1[i] = 0.f; g_sq1[i] = 0.f; g_sum2[i] = 0.f; g_sq2[i] = 0.f; }
    if (i < P1 * CCAT) {
        int o = i / CCAT, c = i % CCAT;
        __half h = __float2half_rn(W1[i]);
        if (c < CIN) g_W1a[c * P1 + o] = h;
        else         g_W1b[(c - CIN) * P1 + o] = h;
    }
    if (i < P2 * P1) {
        int o = i / P1, c = i % P1;
        g_W2[c * P2 + o] = __float2half_rn(W2[i]);
    }
}

// ---------------- three_nn: 2 m-points per thread ----------------
__global__ void knn_kernel(const float* __restrict__ xyzs, const float* __restrict__ oxyzs) {
    __shared__ float sx[NPTS], sy[NPTS], sz[NPTS];
    int f = blockIdx.y;
    const float* p = xyzs + (size_t)f * NPTS * 3;
    for (int i = threadIdx.x; i < NPTS; i += 256) {
        sx[i] = p[3 * i]; sy[i] = p[3 * i + 1]; sz[i] = p[3 * i + 2];
    }
    __syncthreads();
    int m1 = blockIdx.x * 256 + threadIdx.x;
    int m2 = m1 + 2048;
    const float* q1 = oxyzs + ((size_t)f * MPTS + m1) * 3;
    const float* q2 = oxyzs + ((size_t)f * MPTS + m2) * 3;
    float ax = q1[0], ay = q1[1], az = q1[2];
    float cx = q2[0], cy = q2[1], cz = q2[2];
    float p0 = 1e30f, p1_ = 1e30f, p2_ = 1e30f;
    int   pi0 = 0,    pi1 = 0,    pi2 = 0;
    float r0 = 1e30f, r1 = 1e30f, r2 = 1e30f;
    int   ri0 = 0,    ri1 = 0,    ri2 = 0;
    #pragma unroll 4
    for (int n = 0; n < NPTS; n++) {
        float x = sx[n], y = sy[n], z = sz[n];
        float dx = ax - x, dy = ay - y, dz = az - z;
        float d = fmaf(dx, dx, fmaf(dy, dy, dz * dz));
        if (d < p2_) {
            if (d < p1_) {
                p2_ = p1_; pi2 = pi1;
                if (d < p0) { p1_ = p0; pi1 = pi0; p0 = d; pi0 = n; }
                else        { p1_ = d;  pi1 = n; }
            } else { p2_ = d; pi2 = n; }
        }
        float ex = cx - x, ey = cy - y, ez = cz - z;
        float e = fmaf(ex, ex, fmaf(ey, ey, ez * ez));
        if (e < r2) {
            if (e < r1) {
                r2 = r1; ri2 = ri1;
                if (e < r0) { r1 = r0; ri1 = ri0; r0 = e; ri0 = n; }
                else        { r1 = e;  ri1 = n; }
            } else { r2 = e; ri2 = n; }
        }
    }
    {
        float w0 = 1.f / (p0 + EPS_D), w1 = 1.f / (p1_ + EPS_D), w2 = 1.f / (p2_ + EPS_D);
        float inv = 1.f / (w0 + w1 + w2);
        size_t base = ((size_t)f * MPTS + m1) * 3;
        g_idx[base] = pi0; g_idx[base + 1] = pi1; g_idx[base + 2] = pi2;
        g_w[base] = w0 * inv; g_w[base + 1] = w1 * inv; g_w[base + 2] = w2 * inv;
    }
    {
        float w0 = 1.f / (r0 + EPS_D), w1 = 1.f / (r1 + EPS_D), w2 = 1.f / (r2 + EPS_D);
        float inv = 1.f / (w0 + w1 + w2);
        size_t base = ((size_t)f * MPTS + m2) * 3;
        g_idx[base] = ri0; g_idx[base + 1] = ri1; g_idx[base + 2] = ri2;
        g_w[base] = w0 * inv; g_w[base + 1] = w1 * inv; g_w[base + 2] = w2 * inv;
    }
}

// ======== GEMM A (gemmZ / gemmB): CTA 32(M) x 128(N), 8 warps 1x8, warp tile 32x16 ========
// (R13-validated) A [k][m] via cp.async + smem split transform; B fp16 via cp.async.
#define A0_ABF  2560      // fp16 A buf: 32k x 80B
#define A0_AFB  4608      // fp32 A buf: 32k x 144B
#define A0_AL   (2 * A0_ABF)
#define A0_AF   (4 * A0_ABF)
#define A0_BH   (A0_AF + 2 * A0_AFB)     // 19456
#define SMEM_A0 (A0_BH + 2 * 8704)       // 36864

template <int K, int FUSE, int MTOT>
__device__ __forceinline__ void gemm_mma0(const float* __restrict__ Aall,
                                          const __half* __restrict__ Ball,
                                          float* __restrict__ Call) {
    extern __shared__ char sm[];
    const uint32_t sbase = smem_u32(sm);
    constexpr int NC = K / 32;

    const int tid = threadIdx.x;
    const int l   = tid & 31;
    const int wn  = tid >> 5;        // 0..7
    const int f   = blockIdx.z, t = f & 3;
    const int bm  = blockIdx.y * 32;
    const int bn0 = blockIdx.x * 128;
    const float* A = Aall + (size_t)f * MTOT * K;
    float*       C = Call + (size_t)f * MTOT * 256;

    const uint32_t aoff = (uint32_t)(((l & 7) + ((l >> 4) & 1) * 8) * 80 + ((l >> 3) & 1) * 16);
    const uint32_t boff = (uint32_t)((((l & 7) + ((l >> 3) & 1) * 8) * 136 +
                                      (l >> 4) * 8 + wn * 16) * 2);

    float acc[2][2][4];
    #pragma unroll
    for (int i = 0; i < 2; i++)
        #pragma unroll
        for (int j = 0; j < 2; j++)
            #pragma unroll
            for (int k = 0; k < 4; k++) acc[i][j][k] = 0.f;

    auto issueB = [&](int kc, int bb) {
        int r  = tid >> 3;
        int ce = (tid & 7) * 16;
        const __half* sh = Ball + (size_t)(kc * 32 + r) * 256 + bn0 + ce;
        uint32_t dh = sbase + A0_BH + bb * 8704 + (uint32_t)(r * 272 + ce * 2);
        CP_ASYNC16(dh,      sh);
        CP_ASYNC16(dh + 16, sh + 8);
    };
    auto issueAf = [&](int kc, int fb) {
        int r  = tid >> 3;
        int c4 = (tid & 7) * 4;
        const float* s = A + (size_t)(kc * 32 + r) * MTOT + bm + c4;
        uint32_t dd = sbase + A0_AF + fb * A0_AFB + (uint32_t)(r * 144 + c4 * 4);
        CP_ASYNC16(dd, s);
    };
    auto transform = [&](int fb, int ab) {
        int r = tid >> 3;
        int c = (tid & 7) * 4;
        uint32_t srcb = (uint32_t)(A0_AF + fb * A0_AFB + r * 144 + c * 4);
        float4 v = *(const float4*)(sm + srcb);
        uint32_t h0, l0, h1, l1;
        split2(v.x, v.y, h0, l0); split2(v.z, v.w, h1, l1);
        uint32_t dst = (uint32_t)(ab * A0_ABF + r * 80 + c * 2);
        *(uint2*)(sm + dst)         = make_uint2(h0, h1);
        *(uint2*)(sm + A0_AL + dst) = make_uint2(l0, l1);
    };
    auto compute = [&](int buf) {
        #pragma unroll
        for (int ks = 0; ks < 2; ks++) {
            uint32_t bh[4];
            LDMX4T(bh, sbase + A0_BH + buf * 8704 + boff + ks * 4352);
            #pragma unroll
            for (int mi = 0; mi < 2; mi++) {
                uint32_t ah[4], al[4];
                uint32_t ad = sbase + buf * A0_ABF + aoff + mi * 32 + ks * 1280;
                LDMX4T(ah, ad);
                LDMX4T(al, ad + A0_AL);
                MMA_F16(acc[mi][0], ah, bh[0], bh[1]);
                MMA_F16(acc[mi][1], ah, bh[2], bh[3]);
                MMA_F16(acc[mi][0], al, bh[0], bh[1]);
                MMA_F16(acc[mi][1], al, bh[2], bh[3]);
            }
        }
    };

    issueAf(0, 0); CP_COMMIT();
    issueB(0, 0); issueAf(1, 1); CP_COMMIT();
    CP_WAIT1();
    __syncthreads();
    transform(0, 0);
    for (int kc = 0; kc < NC; kc++) {
        CP_WAIT0();
        __syncthreads();
        if (kc + 1 < NC) {
            transform((kc + 1) & 1, (kc + 1) & 1);
            issueB(kc + 1, (kc + 1) & 1);
            if (kc + 2 < NC) issueAf(kc + 2, kc & 1);
            CP_COMMIT();
        }
        compute(kc & 1);
    }

    if (FUSE == 1) {
        __syncthreads();
        float* smf = (float*)sm;
        #pragma unroll
        for (int ni = 0; ni < 2; ni++) {
            int c = wn * 16 + ni * 8 + (l & 3) * 2;
            #pragma unroll
            for (int mi = 0; mi < 2; mi++) {
                int r = mi * 16 + (l >> 2);
                *(float2*)&smf[r * 136 + c]       = make_float2(acc[mi][ni][0], acc[mi][ni][1]);
                *(float2*)&smf[(r + 8) * 136 + c] = make_float2(acc[mi][ni][2], acc[mi][ni][3]);
            }
        }
        __syncthreads();
        const int oc = tid & 127, half = tid >> 7;
        const int o  = bn0 + oc;
        const float* Z = g_ZT + (size_t)f * NPTS * 256;
        float s = 0.f, q = 0.f;
        #pragma unroll 4
        for (int rr = 0; rr < 16; rr++) {
            int r = half * 16 + rr;
            int m = bm + r;
            size_t ib = ((size_t)f * MPTS + m) * 3;
            int   i0 = g_idx[ib], i1 = g_idx[ib + 1], i2 = g_idx[ib + 2];
            float w0 = g_w[ib],   w1 = g_w[ib + 1],   w2 = g_w[ib + 2];
            float v = smf[r * 136 + oc];
            v = fmaf(w0, Z[(size_t)i0 * 256 + o], v);
            v = fmaf(w1, Z[(size_t)i1 * 256 + o], v);
            v = fmaf(w2, Z[(size_t)i2 * 256 + o], v);
            g_y1[((size_t)f * MPTS + m) * 256 + o] = v;
            s += v; q = fmaf(v, v, q);
        }
        atomicAdd(&g_sum1[t * 256 + o], s);
        atomicAdd(&g_sq1 [t * 256 + o], q);
    } else {
        #pragma unroll
        for (int ni = 0; ni < 2; ni++) {
            int col = bn0 + wn * 16 + ni * 8 + (l & 3) * 2;
            #pragma unroll
            for (int mi = 0; mi < 2; mi++) {
                int row = bm + mi * 16 + (l >> 2);
                float* cp = C + (size_t)row * 256 + col;
                *(float2*)cp          = make_float2(acc[mi][ni][0], acc[mi][ni][1]);
                *(float2*)(cp + 2048) = make_float2(acc[mi][ni][2], acc[mi][ni][3]);
            }
        }
    }
}

__global__ void __launch_bounds__(256, 4) gemmZ_mma(const float* __restrict__ feats) {
    gemm_mma0<CIN, 0, NPTS>(feats, g_W1a, g_ZT);
}
__global__ void __launch_bounds__(256, 4) gemmB_mma(const float* __restrict__ ofeat) {
    gemm_mma0<CORIG, 1, MPTS>(ofeat, g_W1b, g_y1);
}

// ======== GEMM 2: CTA 64(M) x 128(N), 8 warps 2x4, warp tile 32x32, occ 3 ========
// A = y1 [m][k] via cp.async + smem transform (BN1+ReLU+split in transform):
// no global latency on the barrier path. B fp16 via cp.async; stats2 fused.
// smem = 58368 B -> 3 CTAs/SM (R7's variant had 75.8KB -> occ 2; now fixed).
#define G2_ABF  5120      // fp16 A buf: 64 rows x 80B
#define G2_AFB  9216      // fp32 A buf: 64 rows x 144B
#define G2_AL   (2 * G2_ABF)
#define G2_AF   (4 * G2_ABF)             // 20480
#define G2_BH   (G2_AF + 2 * G2_AFB)     // 38912
#define G2_SC   (G2_BH + 2 * 8704)       // 56320
#define SMEM_A1 (G2_SC + 2048)           // 58368

__global__ void __launch_bounds__(256, 3) gemm2_mma() {
    extern __shared__ char sm[];
    const uint32_t sbase = smem_u32(sm);
    constexpr int K = P1, NC = K / 32;

    const int tid = threadIdx.x;
    const int l   = tid & 31;
    const int wid = tid >> 5;
    const int wm  = wid >> 2;       // 0..1
    const int wn  = wid & 3;        // 0..3
    const int f   = blockIdx.z, t = f & 3;
    const int bm  = blockIdx.y * 64;
    const int bn0 = blockIdx.x * 128;
    const float* A = g_y1 + (size_t)f * MPTS * K;
    float*       C = g_y2 + (size_t)f * MPTS * 256;

    float* s_sc = (float*)(sm + G2_SC);
    float* s_bi = (float*)(sm + G2_SC + 1024);
    s_sc[tid] = g_a1[t * 256 + tid];
    s_bi[tid] = g_b1[t * 256 + tid];
    // prologue __syncthreads() (below) makes the coef table visible before transform(0)

    const uint32_t aoff = (uint32_t)((l & 15) * 80 + (l >> 4) * 16 + wm * 2560);
    const uint32_t boff = (uint32_t)((((l & 7) + ((l >> 3) & 1) * 8) * 136 +
                                      (l >> 4) * 8 + wn * 32) * 2);

    float acc[2][4][4];
    #pragma unroll
    for (int i = 0; i < 2; i++)
        #pragma unroll
        for (int j = 0; j < 4; j++)
            #pragma unroll
            for (int k = 0; k < 4; k++) acc[i][j][k] = 0.f;

    auto issueB = [&](int kc, int bb) {
        int r  = tid >> 3;
        int ce = (tid & 7) * 16;
        const __half* sh = g_W2 + (size_t)(kc * 32 + r) * 256 + bn0 + ce;
        uint32_t dh = sbase + G2_BH + bb * 8704 + (uint32_t)(r * 272 + ce * 2);
        CP_ASYNC16(dh,      sh);
        CP_ASYNC16(dh + 16, sh + 8);
    };
    auto issueAf = [&](int kc, int fb) {
        int r  = tid >> 2;                 // m row 0..63
        int c8 = (tid & 3) * 8;            // k col
        const float* s = A + (size_t)(bm + r) * K + kc * 32 + c8;
        uint32_t dd = sbase + G2_AF + fb * G2_AFB + (uint32_t)(r * 144 + c8 * 4);
        CP_ASYNC16(dd, s);
        CP_ASYNC16(dd + 16, s + 4);
    };
    auto transform = [&](int kc, int fb, int ab) {
        int r = tid >> 2;
        int c = (tid & 3) * 8;
        uint32_t srcb = (uint32_t)(G2_AF + fb * G2_AFB + r * 144 + c * 4);
        float4 v0 = *(const float4*)(sm + srcb);
        float4 v1 = *(const float4*)(sm + srcb + 16);
        int cc = kc * 32 + c;
        v0.x = fmaxf(0.f, fmaf(s_sc[cc + 0], v0.x, s_bi[cc + 0]));
        v0.y = fmaxf(0.f, fmaf(s_sc[cc + 1], v0.y, s_bi[cc + 1]));
        v0.z = fmaxf(0.f, fmaf(s_sc[cc + 2], v0.z, s_bi[cc + 2]));
        v0.w = fmaxf(0.f, fmaf(s_sc[cc + 3], v0.w, s_bi[cc + 3]));
        v1.x = fmaxf(0.f, fmaf(s_sc[cc + 4], v1.x, s_bi[cc + 4]));
        v1.y = fmaxf(0.f, fmaf(s_sc[cc + 5], v1.y, s_bi[cc + 5]));
        v1.z = fmaxf(0.f, fmaf(s_sc[cc + 6], v1.z, s_bi[cc + 6]));
        v1.w = fmaxf(0.f, fmaf(s_sc[cc + 7], v1.w, s_bi[cc + 7]));
        uint32_t h0, l0, h1, l1, h2, l2, h3, l3;
        split2(v0.x, v0.y, h0, l0); split2(v0.z, v0.w, h1, l1);
        split2(v1.x, v1.y, h2, l2); split2(v1.z, v1.w, h3, l3);
        uint32_t dst = (uint32_t)(ab * G2_ABF + r * 80 + c * 2);
        *(uint4*)(sm + dst)         = make_uint4(h0, h1, h2, h3);
        *(uint4*)(sm + G2_AL + dst) = make_uint4(l0, l1, l2, l3);
    };
    auto compute = [&](int buf) {
        #pragma unroll
        for (int ks = 0; ks < 2; ks++) {
            uint32_t ah[4], al[4], ah2[4], al2[4], bh[2][4];
            uint32_t ad = sbase + buf * G2_ABF + aoff + ks * 32;
            LDMX4(ah, ad);
            LDMX4(al, ad + G2_AL);
            LDMX4(ah2, ad + 1280);
            LDMX4(al2, ad + 1280 + G2_AL);
            #pragma unroll
            for (int nf = 0; nf < 2; nf++) {
                uint32_t bd = sbase + G2_BH + buf * 8704 + boff + nf * 32 + ks * 4352;
                LDMX4T(bh[nf], bd);
                const int n0 = nf * 2, n1 = nf * 2 + 1;
                MMA_F16(acc[0][n0], ah,  bh[nf][0], bh[nf][1]);
                MMA_F16(acc[0][n1], ah,  bh[nf][2], bh[nf][3]);
                MMA_F16(acc[1][n0], ah2, bh[nf][0], bh[nf][1]);
                MMA_F16(acc[1][n1], ah2, bh[nf][2], bh[nf][3]);
                MMA_F16(acc[0][n0], al,  bh[nf][0], bh[nf][1]);
                MMA_F16(acc[0][n1], al,  bh[nf][2], bh[nf][3]);
                MMA_F16(acc[1][n0], al2, bh[nf][0], bh[nf][1]);
                MMA_F16(acc[1][n1], al2, bh[nf][2], bh[nf][3]);
            }
        }
    };

    issueAf(0, 0); CP_COMMIT();
    issueB(0, 0); issueAf(1, 1); CP_COMMIT();
    CP_WAIT1();
    __syncthreads();                       // A(0) landed; coef table visible
    transform(0, 0, 0);
    for (int kc = 0; kc < NC; kc++) {
        CP_WAIT0();
        __syncthreads();
        if (kc + 1 < NC) {
            transform(kc + 1, (kc + 1) & 1, (kc + 1) & 1);
            issueB(kc + 1, (kc + 1) & 1);
            if (kc + 2 < NC) issueAf(kc + 2, kc & 1);
            CP_COMMIT();
        }
        compute(kc & 1);
    }

    // epilogue: store + fused stats2
    #pragma unroll
    for (int ni = 0; ni < 4; ni++) {
        int col = bn0 + wn * 32 + ni * 8 + (l & 3) * 2;
        float s0 = 0.f, q0 = 0.f, s1 = 0.f, q1 = 0.f;
        #pragma unroll
        for (int mi = 0; mi < 2; mi++) {
            int row = bm + wm * 32 + mi * 16 + (l >> 2);
            float v0 = acc[mi][ni][0], v1 = acc[mi][ni][1];
            float v2 = acc[mi][ni][2], v3 = acc[mi][ni][3];
            float* cp = C + (size_t)row * 256 + col;
            *(float2*)cp          = make_float2(v0, v1);
            *(float2*)(cp + 2048) = make_float2(v2, v3);
            s0 += v0 + v2; s1 += v1 + v3;
            q0 += fmaf(v0, v0, v2 * v2);
            q1 += fmaf(v1, v1, v3 * v3);
        }
        #pragma unroll
        for (int d = 4; d < 32; d <<= 1) {
            s0 += __shfl_xor_sync(0xffffffffu, s0, d);
            s1 += __shfl_xor_sync(0xffffffffu, s1, d);
            q0 += __shfl_xor_sync(0xffffffffu, q0, d);
            q1 += __shfl_xor_sync(0xffffffffu, q1, d);
        }
        if (l < 4) {
            atomicAdd(&g_sum2[t * 256 + col],     s0);
            atomicAdd(&g_sum2[t * 256 + col + 1], s1);
            atomicAdd(&g_sq2 [t * 256 + col],     q0);
            atomicAdd(&g_sq2 [t * 256 + col + 1], q1);
        }
    }
}

// ---------------- finalize BN coefficients ----------------
__global__ void finalize_kernel(int which, const float* __restrict__ gamma,
                                const float* __restrict__ beta) {
    int i = blockIdx.x * 256 + threadIdx.x;
    if (i >= TT * P1) return;
    const float rcnt = 1.0f / (float)(BB * MPTS);
    float sum = (which == 1) ? g_sum1[i] : g_sum2[i];
    float sq  = (which == 1) ? g_sq1[i]  : g_sq2[i];
    float mean = sum * rcnt;
    float var  = fmaf(-mean, mean, sq * rcnt);
    int o = i & 255;
    float a = gamma[o] * rsqrtf(var + EPS_BN);
    float b = fmaf(-mean, a, beta[o]);
    if (which == 1) { g_a1[i] = a; g_b1[i] = b; }
    else            { g_a2[i] = a; g_b2[i] = b; }
}

// ---------------- output: BN2+ReLU + transpose [f][m][o] -> [f][o][m] ----------------
__global__ void output_kernel(float* __restrict__ out) {
    __shared__ float tile[32][33];
    int f = blockIdx.z, t = f & 3;
    int m0 = blockIdx.x * 32, o0 = blockIdx.y * 32;
    int tx = threadIdx.x, ty = threadIdx.y;
    #pragma unroll
    for (int i = ty; i < 32; i += 8) {
        int o = o0 + tx;
        float v = g_y2[((size_t)f * MPTS + m0 + i) * P2 + o];
        tile[i][tx] = fmaxf(0.f, fmaf(g_a2[t * P2 + o], v, g_b2[t * P2 + o]));
    }
    __syncthreads();
    #pragma unroll
    for (int i = ty; i < 32; i += 8)
        out[((size_t)f * P2 + o0 + i) * MPTS + m0 + tx] = tile[tx][i];
}

// ---------------- launch ----------------
extern "C" void kernel_launch(void* const* d_in, const int* in_sizes, int n_in,
                              void* d_out, int out_size) {
    const float* xyzs   = (const float*)d_in[0];
    const float* oxyzs  = (const float*)d_in[1];
    const float* feats  = (const float*)d_in[2];
    const float* ofeat  = (const float*)d_in[3];
    const float* W1     = (const float*)d_in[4];
    const float* gamma1 = (const float*)d_in[5];
    const float* beta1  = (const float*)d_in[6];
    const float* W2     = (const float*)d_in[7];
    const float* gamma2 = (const float*)d_in[8];
    const float* beta2  = (const float*)d_in[9];
    float* out = (float*)d_out;

    (void)cudaFuncSetAttribute(gemmZ_mma, cudaFuncAttributeMaxDynamicSharedMemorySize, SMEM_A0);
    (void)cudaFuncSetAttribute(gemmB_mma, cudaFuncAttributeMaxDynamicSharedMemorySize, SMEM_A0);
    (void)cudaFuncSetAttribute(gemm2_mma, cudaFuncAttributeMaxDynamicSharedMemorySize, SMEM_A1);

    const int xyz_elems = FRAMES * MPTS * 3;
    const int x_elems   = FRAMES * P2 * MPTS;
    float* out_x = out;
    if (out_size >= xyz_elems + x_elems) {
        cudaMemcpyAsync(out, oxyzs, (size_t)xyz_elems * sizeof(float),
                        cudaMemcpyDeviceToDevice, 0);
        out_x = out + xyz_elems;
    }

    prep_kernel<<<384, 256>>>(W1, W2);
    knn_kernel<<<dim3(MPTS / 512, FRAMES), 256>>>(xyzs, oxyzs);

    gemmZ_mma<<<dim3(2, NPTS / 32, FRAMES), 256, SMEM_A0>>>(feats);   // Z = feats^T @ W1a
    gemmB_mma<<<dim3(2, MPTS / 32, FRAMES), 256, SMEM_A0>>>(ofeat);   // y1 + gather(Z); stats1
    finalize_kernel<<<4, 256>>>(1, gamma1, beta1);

    gemm2_mma<<<dim3(2, MPTS / 64, FRAMES), 256, SMEM_A1>>>();        // y2 = relu(bn1(y1)) @ W2; stats2
    finalize_kernel<<<4, 256>>>(2, gamma2, beta2);

    output_kernel<<<dim3(MPTS / 32, P2 / 32, FRAMES), dim3(32, 8)>>>(out_x);
}

// round 17
// speedup vs baseline: 1.2324x; 1.0642x over previous
#include <cuda_runtime.h>
#include <cuda_fp16.h>
#include <stdint.h>
#include <math.h>

// ---------------- problem constants ----------------
#define BB      8
#define TT      4
#define NPTS    1024
#define MPTS    4096
#define CIN     256
#define CORIG   128
#define CCAT    384
#define P1      256
#define P2      256
#define FRAMES  32          // B*T
#define EPS_D   1e-8f
#define EPS_BN  1e-5f

// ---------------- scratch (device globals, no runtime alloc) ----------------
__device__ __align__(16) int   g_idx[FRAMES * MPTS * 3];
__device__ __align__(16) float g_w  [FRAMES * MPTS * 3];
__device__ __align__(16) float g_ZT [(size_t)FRAMES * NPTS * P1];     // [f][n][o]
__device__ __align__(16) float g_y1 [(size_t)FRAMES * MPTS * P1];     // [f][m][o]
__device__ __align__(16) float g_y2 [(size_t)FRAMES * MPTS * P2];     // [f][m][o]
// fp16 weights, [k][n] layout (n contiguous)
__device__ __align__(16) __half g_W1a[CIN * P1];
__device__ __align__(16) __half g_W1b[CORIG * P1];
__device__ __align__(16) __half g_W2 [P1 * P2];
__device__ float g_sum1[TT * P1], g_sq1[TT * P1], g_a1[TT * P1], g_b1[TT * P1];
__device__ float g_sum2[TT * P2], g_sq2[TT * P2], g_a2[TT * P2], g_b2[TT * P2];

// ---------------- helpers ----------------
__device__ __forceinline__ uint32_t smem_u32(const void* p) {
    uint32_t a;
    asm("{ .reg .u64 t; cvta.to.shared.u64 t, %1; cvt.u32.u64 %0, t; }" : "=r"(a) : "l"(p));
    return a;
}

#define LDMX4(r, addr) \
    asm volatile("ldmatrix.sync.aligned.m8n8.x4.shared.b16 {%0,%1,%2,%3}, [%4];" \
        : "=r"((r)[0]), "=r"((r)[1]), "=r"((r)[2]), "=r"((r)[3]) : "r"(addr))

#define LDMX4T(r, addr) \
    asm volatile("ldmatrix.sync.aligned.m8n8.x4.trans.shared.b16 {%0,%1,%2,%3}, [%4];" \
        : "=r"((r)[0]), "=r"((r)[1]), "=r"((r)[2]), "=r"((r)[3]) : "r"(addr))

#define MMA_F16(d, a, b0, b1) \
    asm volatile("mma.sync.aligned.m16n8k16.row.col.f32.f16.f16.f32 " \
        "{%0,%1,%2,%3},{%4,%5,%6,%7},{%8,%9},{%0,%1,%2,%3};" \
        : "+f"((d)[0]), "+f"((d)[1]), "+f"((d)[2]), "+f"((d)[3]) \
        : "r"((a)[0]), "r"((a)[1]), "r"((a)[2]), "r"((a)[3]), "r"(b0), "r"(b1))

#define CP_ASYNC16(dst, src) \
    asm volatile("cp.async.cg.shared.global [%0], [%1], 16;" :: "r"(dst), "l"(src))
#define CP_COMMIT()  asm volatile("cp.async.commit_group;" ::: "memory")
#define CP_WAIT0()   asm volatile("cp.async.wait_group 0;" ::: "memory")
#define CP_WAIT1()   asm volatile("cp.async.wait_group 1;" ::: "memory")

__device__ __forceinline__ uint32_t pack2(float a, float b) {
    __half2 h = __floats2half2_rn(a, b);
    return *reinterpret_cast<uint32_t*>(&h);
}

// ---------------- prep ----------------
__global__ void prep_kernel(const float* __restrict__ W1, const float* __restrict__ W2) {
    int i = blockIdx.x * 256 + threadIdx.x;
    if (i < TT * P1) { g_sum1[i] = 0.f; g_sq1[i] = 0.f; g_sum2[i] = 0.f; g_sq2[i] = 0.f; }
    if (i < P1 * CCAT) {
        int o = i / CCAT, c = i % CCAT;
        __half h = __float2half_rn(W1[i]);
        if (c < CIN) g_W1a[c * P1 + o] = h;
        else         g_W1b[(c - CIN) * P1 + o] = h;
    }
    if (i < P2 * P1) {
        int o = i / P1, c = i % P1;
        g_W2[c * P2 + o] = __float2half_rn(W2[i]);
    }
}

// ---------------- three_nn: 2 m-points per thread ----------------
__global__ void knn_kernel(const float* __restrict__ xyzs, const float* __restrict__ oxyzs) {
    __shared__ float sx[NPTS], sy[NPTS], sz[NPTS];
    int f = blockIdx.y;
    const float* p = xyzs + (size_t)f * NPTS * 3;
    for (int i = threadIdx.x; i < NPTS; i += 256) {
        sx[i] = p[3 * i]; sy[i] = p[3 * i + 1]; sz[i] = p[3 * i + 2];
    }
    __syncthreads();
    int m1 = blockIdx.x * 256 + threadIdx.x;
    int m2 = m1 + 2048;
    const float* q1 = oxyzs + ((size_t)f * MPTS + m1) * 3;
    const float* q2 = oxyzs + ((size_t)f * MPTS + m2) * 3;
    float ax = q1[0], ay = q1[1], az = q1[2];
    float cx = q2[0], cy = q2[1], cz = q2[2];
    float p0 = 1e30f, p1_ = 1e30f, p2_ = 1e30f;
    int   pi0 = 0,    pi1 = 0,    pi2 = 0;
    float r0 = 1e30f, r1 = 1e30f, r2 = 1e30f;
    int   ri0 = 0,    ri1 = 0,    ri2 = 0;
    #pragma unroll 4
    for (int n = 0; n < NPTS; n++) {
        float x = sx[n], y = sy[n], z = sz[n];
        float dx = ax - x, dy = ay - y, dz = az - z;
        float d = fmaf(dx, dx, fmaf(dy, dy, dz * dz));
        if (d < p2_) {
            if (d < p1_) {
                p2_ = p1_; pi2 = pi1;
                if (d < p0) { p1_ = p0; pi1 = pi0; p0 = d; pi0 = n; }
                else        { p1_ = d;  pi1 = n; }
            } else { p2_ = d; pi2 = n; }
        }
        float ex = cx - x, ey = cy - y, ez = cz - z;
        float e = fmaf(ex, ex, fmaf(ey, ey, ez * ez));
        if (e < r2) {
            if (e < r1) {
                r2 = r1; ri2 = ri1;
                if (e < r0) { r1 = r0; ri1 = ri0; r0 = e; ri0 = n; }
                else        { r1 = e;  ri1 = n; }
            } else { r2 = e; ri2 = n; }
        }
    }
    {
        float w0 = 1.f / (p0 + EPS_D), w1 = 1.f / (p1_ + EPS_D), w2 = 1.f / (p2_ + EPS_D);
        float inv = 1.f / (w0 + w1 + w2);
        size_t base = ((size_t)f * MPTS + m1) * 3;
        g_idx[base] = pi0; g_idx[base + 1] = pi1; g_idx[base + 2] = pi2;
        g_w[base] = w0 * inv; g_w[base + 1] = w1 * inv; g_w[base + 2] = w2 * inv;
    }
    {
        float w0 = 1.f / (r0 + EPS_D), w1 = 1.f / (r1 + EPS_D), w2 = 1.f / (r2 + EPS_D);
        float inv = 1.f / (w0 + w1 + w2);
        size_t base = ((size_t)f * MPTS + m2) * 3;
        g_idx[base] = ri0; g_idx[base + 1] = ri1; g_idx[base + 2] = ri2;
        g_w[base] = w0 * inv; g_w[base + 1] = w1 * inv; g_w[base + 2] = w2 * inv;
    }
}

// ======== GEMM A (gemmZ / gemmB): CTA 32(M) x 128(N), 8 warps 1x8, warp tile 32x16 ========
// Pure fp16 x fp16: A [k][m] via cp.async + smem cvt transform; B fp16 via cp.async.
// Per chunk/warp: 6 LDSM.x4 + 8 MMA.
#define A0_ABF  2560      // fp16 A buf: 32k x 80B
#define A0_AFB  4608      // fp32 A buf: 32k x 144B
#define A0_AF   (2 * A0_ABF)             // 5120
#define A0_BH   (A0_AF + 2 * A0_AFB)     // 14336
#define SMEM_A0 (A0_BH + 2 * 8704)       // 31744

template <int K, int FUSE, int MTOT>
__device__ __forceinline__ void gemm_mma0(const float* __restrict__ Aall,
                                          const __half* __restrict__ Ball,
                                          float* __restrict__ Call) {
    extern __shared__ char sm[];
    const uint32_t sbase = smem_u32(sm);
    constexpr int NC = K / 32;

    const int tid = threadIdx.x;
    const int l   = tid & 31;
    const int wn  = tid >> 5;        // 0..7
    const int f   = blockIdx.z, t = f & 3;
    const int bm  = blockIdx.y * 32;
    const int bn0 = blockIdx.x * 128;
    const float* A = Aall + (size_t)f * MTOT * K;
    float*       C = Call + (size_t)f * MTOT * 256;

    const uint32_t aoff = (uint32_t)(((l & 7) + ((l >> 4) & 1) * 8) * 80 + ((l >> 3) & 1) * 16);
    const uint32_t boff = (uint32_t)((((l & 7) + ((l >> 3) & 1) * 8) * 136 +
                                      (l >> 4) * 8 + wn * 16) * 2);

    float acc[2][2][4];
    #pragma unroll
    for (int i = 0; i < 2; i++)
        #pragma unroll
        for (int j = 0; j < 2; j++)
            #pragma unroll
            for (int k = 0; k < 4; k++) acc[i][j][k] = 0.f;

    auto issueB = [&](int kc, int bb) {
        int r  = tid >> 3;
        int ce = (tid & 7) * 16;
        const __half* sh = Ball + (size_t)(kc * 32 + r) * 256 + bn0 + ce;
        uint32_t dh = sbase + A0_BH + bb * 8704 + (uint32_t)(r * 272 + ce * 2);
        CP_ASYNC16(dh,      sh);
        CP_ASYNC16(dh + 16, sh + 8);
    };
    auto issueAf = [&](int kc, int fb) {
        int r  = tid >> 3;
        int c4 = (tid & 7) * 4;
        const float* s = A + (size_t)(kc * 32 + r) * MTOT + bm + c4;
        uint32_t dd = sbase + A0_AF + fb * A0_AFB + (uint32_t)(r * 144 + c4 * 4);
        CP_ASYNC16(dd, s);
    };
    auto transform = [&](int fb, int ab) {
        int r = tid >> 3;
        int c = (tid & 7) * 4;
        uint32_t srcb = (uint32_t)(A0_AF + fb * A0_AFB + r * 144 + c * 4);
        float4 v = *(const float4*)(sm + srcb);
        uint32_t dst = (uint32_t)(ab * A0_ABF + r * 80 + c * 2);
        *(uint2*)(sm + dst) = make_uint2(pack2(v.x, v.y), pack2(v.z, v.w));
    };
    auto compute = [&](int buf) {
        #pragma unroll
        for (int ks = 0; ks < 2; ks++) {
            uint32_t bh[4];
            LDMX4T(bh, sbase + A0_BH + buf * 8704 + boff + ks * 4352);
            #pragma unroll
            for (int mi = 0; mi < 2; mi++) {
                uint32_t ah[4];
                LDMX4T(ah, sbase + buf * A0_ABF + aoff + mi * 32 + ks * 1280);
                MMA_F16(acc[mi][0], ah, bh[0], bh[1]);
                MMA_F16(acc[mi][1], ah, bh[2], bh[3]);
            }
        }
    };

    issueAf(0, 0); CP_COMMIT();
    issueB(0, 0); issueAf(1, 1); CP_COMMIT();
    CP_WAIT1();
    __syncthreads();
    transform(0, 0);
    for (int kc = 0; kc < NC; kc++) {
        CP_WAIT0();
        __syncthreads();
        if (kc + 1 < NC) {
            transform((kc + 1) & 1, (kc + 1) & 1);
            issueB(kc + 1, (kc + 1) & 1);
            if (kc + 2 < NC) issueAf(kc + 2, kc & 1);
            CP_COMMIT();
        }
        compute(kc & 1);
    }

    if (FUSE == 1) {
        __syncthreads();
        float* smf = (float*)sm;
        #pragma unroll
        for (int ni = 0; ni < 2; ni++) {
            int c = wn * 16 + ni * 8 + (l & 3) * 2;
            #pragma unroll
            for (int mi = 0; mi < 2; mi++) {
                int r = mi * 16 + (l >> 2);
                *(float2*)&smf[r * 136 + c]       = make_float2(acc[mi][ni][0], acc[mi][ni][1]);
                *(float2*)&smf[(r + 8) * 136 + c] = make_float2(acc[mi][ni][2], acc[mi][ni][3]);
            }
        }
        __syncthreads();
        const int oc = tid & 127, half = tid >> 7;
        const int o  = bn0 + oc;
        const float* Z = g_ZT + (size_t)f * NPTS * 256;
        float s = 0.f, q = 0.f;
        #pragma unroll 4
        for (int rr = 0; rr < 16; rr++) {
            int r = half * 16 + rr;
            int m = bm + r;
            size_t ib = ((size_t)f * MPTS + m) * 3;
            int   i0 = g_idx[ib], i1 = g_idx[ib + 1], i2 = g_idx[ib + 2];
            float w0 = g_w[ib],   w1 = g_w[ib + 1],   w2 = g_w[ib + 2];
            float v = smf[r * 136 + oc];
            v = fmaf(w0, Z[(size_t)i0 * 256 + o], v);
            v = fmaf(w1, Z[(size_t)i1 * 256 + o], v);
            v = fmaf(w2, Z[(size_t)i2 * 256 + o], v);
            g_y1[((size_t)f * MPTS + m) * 256 + o] = v;
            s += v; q = fmaf(v, v, q);
        }
        atomicAdd(&g_sum1[t * 256 + o], s);
        atomicAdd(&g_sq1 [t * 256 + o], q);
    } else {
        #pragma unroll
        for (int ni = 0; ni < 2; ni++) {
            int col = bn0 + wn * 16 + ni * 8 + (l & 3) * 2;
            #pragma unroll
            for (int mi = 0; mi < 2; mi++) {
                int row = bm + mi * 16 + (l >> 2);
                float* cp = C + (size_t)row * 256 + col;
                *(float2*)cp          = make_float2(acc[mi][ni][0], acc[mi][ni][1]);
                *(float2*)(cp + 2048) = make_float2(acc[mi][ni][2], acc[mi][ni][3]);
            }
        }
    }
}

__global__ void __launch_bounds__(256, 4) gemmZ_mma(const float* __restrict__ feats) {
    gemm_mma0<CIN, 0, NPTS>(feats, g_W1a, g_ZT);
}
__global__ void __launch_bounds__(256, 4) gemmB_mma(const float* __restrict__ ofeat) {
    gemm_mma0<CORIG, 1, MPTS>(ofeat, g_W1b, g_y1);
}

// ======== GEMM 2: CTA 64(M) x 128(N), 8 warps 2x4, warp tile 32x32, occ 3 ========
// Pure fp16 x fp16: A [m][k] reg prefetch + fused BN1+ReLU (cvt only); B cp.async.
// Per chunk/warp: 8 LDSM.x4 + 16 MMA. stats2 fused in epilogue.
#define G2_ABF  5120      // fp16 A buf: 64 rows x 80B
#define G2_BH   (2 * G2_ABF)             // 10240
#define G2_SC   (G2_BH + 2 * 8704)       // 27648
#define SMEM_A1 (G2_SC + 2048)           // 29696

__global__ void __launch_bounds__(256, 3) gemm2_mma() {
    extern __shared__ char sm[];
    const uint32_t sbase = smem_u32(sm);
    constexpr int K = P1, NC = K / 32;

    const int tid = threadIdx.x;
    const int l   = tid & 31;
    const int wid = tid >> 5;
    const int wm  = wid >> 2;       // 0..1
    const int wn  = wid & 3;        // 0..3
    const int f   = blockIdx.z, t = f & 3;
    const int bm  = blockIdx.y * 64;
    const int bn0 = blockIdx.x * 128;
    const float* A = g_y1 + (size_t)f * MPTS * K;
    float*       C = g_y2 + (size_t)f * MPTS * 256;

    float* s_sc = (float*)(sm + G2_SC);
    float* s_bi = (float*)(sm + G2_SC + 1024);
    s_sc[tid] = g_a1[t * 256 + tid];
    s_bi[tid] = g_b1[t * 256 + tid];
    __syncthreads();

    const uint32_t aoff = (uint32_t)((l & 15) * 80 + (l >> 4) * 16 + wm * 2560);
    const uint32_t boff = (uint32_t)((((l & 7) + ((l >> 3) & 1) * 8) * 136 +
                                      (l >> 4) * 8 + wn * 32) * 2);

    float acc[2][4][4];
    #pragma unroll
    for (int i = 0; i < 2; i++)
        #pragma unroll
        for (int j = 0; j < 4; j++)
            #pragma unroll
            for (int k = 0; k < 4; k++) acc[i][j][k] = 0.f;

    float4 ra0, ra1;

    auto issueB = [&](int kc, int bb) {
        int r  = tid >> 3;
        int ce = (tid & 7) * 16;
        const __half* sh = g_W2 + (size_t)(kc * 32 + r) * 256 + bn0 + ce;
        uint32_t dh = sbase + G2_BH + bb * 8704 + (uint32_t)(r * 272 + ce * 2);
        CP_ASYNC16(dh,      sh);
        CP_ASYNC16(dh + 16, sh + 8);
    };
    auto loadA = [&](int kc) {
        const float* ap = A + (size_t)(bm + (tid >> 2)) * K + kc * 32 + (tid & 3) * 8;
        ra0 = *(const float4*)ap;
        ra1 = *(const float4*)(ap + 4);
    };
    auto storeA = [&](int buf, int kc) {
        float4 v0 = ra0, v1 = ra1;
        int cc = kc * 32 + (tid & 3) * 8;
        v0.x = fmaxf(0.f, fmaf(s_sc[cc + 0], v0.x, s_bi[cc + 0]));
        v0.y = fmaxf(0.f, fmaf(s_sc[cc + 1], v0.y, s_bi[cc + 1]));
        v0.z = fmaxf(0.f, fmaf(s_sc[cc + 2], v0.z, s_bi[cc + 2]));
        v0.w = fmaxf(0.f, fmaf(s_sc[cc + 3], v0.w, s_bi[cc + 3]));
        v1.x = fmaxf(0.f, fmaf(s_sc[cc + 4], v1.x, s_bi[cc + 4]));
        v1.y = fmaxf(0.f, fmaf(s_sc[cc + 5], v1.y, s_bi[cc + 5]));
        v1.z = fmaxf(0.f, fmaf(s_sc[cc + 6], v1.z, s_bi[cc + 6]));
        v1.w = fmaxf(0.f, fmaf(s_sc[cc + 7], v1.w, s_bi[cc + 7]));
        uint32_t ao = (uint32_t)(buf * G2_ABF + (tid >> 2) * 80 + (tid & 3) * 16);
        *(uint4*)(sm + ao) = make_uint4(pack2(v0.x, v0.y), pack2(v0.z, v0.w),
                                        pack2(v1.x, v1.y), pack2(v1.z, v1.w));
    };
    auto compute = [&](int buf) {
        #pragma unroll
        for (int ks = 0; ks < 2; ks++) {
            uint32_t ah[4], ah2[4], bh[2][4];
            uint32_t ad = sbase + buf * G2_ABF + aoff + ks * 32;
            LDMX4(ah, ad);
            LDMX4(ah2, ad + 1280);
            #pragma unroll
            for (int nf = 0; nf < 2; nf++) {
                uint32_t bd = sbase + G2_BH + buf * 8704 + boff + nf * 32 + ks * 4352;
                LDMX4T(bh[nf], bd);
                const int n0 = nf * 2, n1 = nf * 2 + 1;
                MMA_F16(acc[0][n0], ah,  bh[nf][0], bh[nf][1]);
                MMA_F16(acc[0][n1], ah,  bh[nf][2], bh[nf][3]);
                MMA_F16(acc[1][n0], ah2, bh[nf][0], bh[nf][1]);
                MMA_F16(acc[1][n1], ah2, bh[nf][2], bh[nf][3]);
            }
        }
    };

    issueB(0, 0); CP_COMMIT();
    loadA(0); storeA(0, 0);
    CP_WAIT0();
    __syncthreads();
    for (int kc = 0; kc < NC; kc++) {
        if (kc + 1 < NC) {
            issueB(kc + 1, (kc + 1) & 1); CP_COMMIT();
            loadA(kc + 1);
        }
        compute(kc & 1);
        if (kc + 1 < NC) {
            storeA((kc + 1) & 1, kc + 1);
            CP_WAIT0();
            __syncthreads();
        }
    }

    #pragma unroll
    for (int ni = 0; ni < 4; ni++) {
        int col = bn0 + wn * 32 + ni * 8 + (l & 3) * 2;
        float s0 = 0.f, q0 = 0.f, s1 = 0.f, q1 = 0.f;
        #pragma unroll
        for (int mi = 0; mi < 2; mi++) {
            int row = bm + wm * 32 + mi * 16 + (l >> 2);
            float v0 = acc[mi][ni][0], v1 = acc[mi][ni][1];
            float v2 = acc[mi][ni][2], v3 = acc[mi][ni][3];
            float* cp = C + (size_t)row * 256 + col;
            *(float2*)cp          = make_float2(v0, v1);
            *(float2*)(cp + 2048) = make_float2(v2, v3);
            s0 += v0 + v2; s1 += v1 + v3;
            q0 += fmaf(v0, v0, v2 * v2);
            q1 += fmaf(v1, v1, v3 * v3);
        }
        #pragma unroll
        for (int d = 4; d < 32; d <<= 1) {
            s0 += __shfl_xor_sync(0xffffffffu, s0, d);
            s1 += __shfl_xor_sync(0xffffffffu, s1, d);
            q0 += __shfl_xor_sync(0xffffffffu, q0, d);
            q1 += __shfl_xor_sync(0xffffffffu, q1, d);
        }
        if (l < 4) {
            atomicAdd(&g_sum2[t * 256 + col],     s0);
            atomicAdd(&g_sum2[t * 256 + col + 1], s1);
            atomicAdd(&g_sq2 [t * 256 + col],     q0);
            atomicAdd(&g_sq2 [t * 256 + col + 1], q1);
        }
    }
}

// ---------------- finalize BN coefficients ----------------
__global__ void finalize_kernel(int which, const float* __restrict__ gamma,
                                const float* __restrict__ beta) {
    int i = blockIdx.x * 256 + threadIdx.x;
    if (i >= TT * P1) return;
    const float rcnt = 1.0f / (float)(BB * MPTS);
    float sum = (which == 1) ? g_sum1[i] : g_sum2[i];
    float sq  = (which == 1) ? g_sq1[i]  : g_sq2[i];
    float mean = sum * rcnt;
    float var  = fmaf(-mean, mean, sq * rcnt);
    int o = i & 255;
    float a = gamma[o] * rsqrtf(var + EPS_BN);
    float b = fmaf(-mean, a, beta[o]);
    if (which == 1) { g_a1[i] = a; g_b1[i] = b; }
    else            { g_a2[i] = a; g_b2[i] = b; }
}

// ---------------- output: BN2+ReLU + transpose [f][m][o] -> [f][o][m] ----------------
__global__ void output_kernel(float* __restrict__ out) {
    __shared__ float tile[32][33];
    int f = blockIdx.z, t = f & 3;
    int m0 = blockIdx.x * 32, o0 = blockIdx.y * 32;
    int tx = threadIdx.x, ty = threadIdx.y;
    #pragma unroll
    for (int i = ty; i < 32; i += 8) {
        int o = o0 + tx;
        float v = g_y2[((size_t)f * MPTS + m0 + i) * P2 + o];
        tile[i][tx] = fmaxf(0.f, fmaf(g_a2[t * P2 + o], v, g_b2[t * P2 + o]));
    }
    __syncthreads();
    #pragma unroll
    for (int i = ty; i < 32; i += 8)
        out[((size_t)f * P2 + o0 + i) * MPTS + m0 + tx] = tile[tx][i];
}

// ---------------- launch ----------------
extern "C" void kernel_launch(void* const* d_in, const int* in_sizes, int n_in,
                              void* d_out, int out_size) {
    const float* xyzs   = (const float*)d_in[0];
    const float* oxyzs  = (const float*)d_in[1];
    const float* feats  = (const float*)d_in[2];
    const float* ofeat  = (const float*)d_in[3];
    const float* W1     = (const float*)d_in[4];
    const float* gamma1 = (const float*)d_in[5];
    const float* beta1  = (const float*)d_in[6];
    const float* W2     = (const float*)d_in[7];
    const float* gamma2 = (const float*)d_in[8];
    const float* beta2  = (const float*)d_in[9];
    float* out = (float*)d_out;

    (void)cudaFuncSetAttribute(gemmZ_mma, cudaFuncAttributeMaxDynamicSharedMemorySize, SMEM_A0);
    (void)cudaFuncSetAttribute(gemmB_mma, cudaFuncAttributeMaxDynamicSharedMemorySize, SMEM_A0);
    (void)cudaFuncSetAttribute(gemm2_mma, cudaFuncAttributeMaxDynamicSharedMemorySize, SMEM_A1);

    const int xyz_elems = FRAMES * MPTS * 3;
    const int x_elems   = FRAMES * P2 * MPTS;
    float* out_x = out;
    if (out_size >= xyz_elems + x_elems) {
        cudaMemcpyAsync(out, oxyzs, (size_t)xyz_elems * sizeof(float),
                        cudaMemcpyDeviceToDevice, 0);
        out_x = out + xyz_elems;
    }

    prep_kernel<<<384, 256>>>(W1, W2);
    knn_kernel<<<dim3(MPTS / 512, FRAMES), 256>>>(xyzs, oxyzs);

    gemmZ_mma<<<dim3(2, NPTS / 32, FRAMES), 256, SMEM_A0>>>(feats);   // Z = feats^T @ W1a
    gemmB_mma<<<dim3(2, MPTS / 32, FRAMES), 256, SMEM_A0>>>(ofeat);   // y1 + gather(Z); stats1
    finalize_kernel<<<4, 256>>>(1, gamma1, beta1);

    gemm2_mma<<<dim3(2, MPTS / 64, FRAMES), 256, SMEM_A1>>>();        // y2 = relu(bn1(y1)) @ W2; stats2
    finalize_kernel<<<4, 256>>>(2, gamma2, beta2);

    output_kernel<<<dim3(MPTS / 32, P2 / 32, FRAMES), dim3(32, 8)>>>(out_x);
}